// round 9
// baseline (speedup 1.0000x reference)
#include <cuda_runtime.h>

// ---------------- problem constants ----------------
#define NN   32768      // total nodes (B*N)
#define NG   8          // graphs
#define NPG  4096       // nodes per graph
#define NE   524288     // total edges
#define FD   128        // feature dim
#define KD   64         // clusters
#define PAD  128        // adjacency slot pad (max degree << 128, Poisson(16))

// output layout (flat float32)
#define PX_OFF 0        // pooled_x   [512*128]
#define OA_OFF 65536    // out_adj    [8*64*64]
#define PB_OFF 98304    // pooled_batch [512]
#define ML_OFF 98816    // mincut_loss
#define OL_OFF 98817    // ortho_loss

#define FULLM 0xffffffffu

// ---------------- device scratch (static, no allocs) ----------------
static __device__ __align__(16) float g_bufA[NN * FD];      // 16 MB
static __device__ __align__(16) float g_bufB[NN * FD];      // 16 MB
static __device__ __align__(16) float g_s_buf[NN * KD];     // 8 MB  (logits -> s_d)
static __device__ __align__(16) float g_As[NN * KD];        // 8 MB
static __device__ __align__(16) float g_out_pool[NG * KD * FD];
static __device__ float g_outadj[NG * KD * KD];
static __device__ float g_ssm[NG * KD * KD];
static __device__ float g_den[NG];
static __device__ float g_mb[NG];
static __device__ float g_ob[NG];
static __device__ float g_dis[NN];
static __device__ float g_doutdeg[NN];
static __device__ int   g_cnt_dst[NN];
static __device__ int   g_cnt_src[NN];
static __device__ int   g_adj_dst[NN * PAD];   // 16 MB
static __device__ int   g_adj_src[NN * PAD];   // 16 MB

__device__ __forceinline__ float* buf_by_id(int id) {
    switch (id) {
        case 0: return g_bufA;
        case 1: return g_bufB;
        case 2: return g_s_buf;
        default: return g_out_pool;
    }
}

// ---------------- zero scratch ----------------
__global__ void k_zero() {
    int i = blockIdx.x * blockDim.x + threadIdx.x;   // 65536 threads
    if (i < NN) {
        g_cnt_dst[i] = 0; g_cnt_src[i] = 0;
        g_outadj[i] = 0.f; g_ssm[i] = 0.f;           // NG*KD*KD == NN
    }
    g_out_pool[i] = 0.f;                             // exactly 65536
    if (i < NG) g_den[i] = 0.f;
}

// ---------------- adjacency build: no histogram, no scan ----------------
__global__ void k_scatter(const int* __restrict__ src, const int* __restrict__ dst) {
    int idx = blockIdx.x * blockDim.x + threadIdx.x;
    int stride = gridDim.x * blockDim.x;
    for (int e = idx; e < NE; e += stride) {
        int s = src[e], d = dst[e];
        int pd = atomicAdd(&g_cnt_dst[d], 1);
        if (pd < PAD) g_adj_dst[d * PAD + pd] = s;
        int ps = atomicAdd(&g_cnt_src[s], 1);
        if (ps < PAD) g_adj_src[s * PAD + ps] = d;
    }
}

// ---------------- dis = rsqrt(indeg+1), doutdeg = outdeg ----------------
__global__ void k_dis() {
    int v = blockIdx.x * blockDim.x + threadIdx.x;
    if (v < NN) {
        g_dis[v] = rsqrtf((float)g_cnt_dst[v] + 1.0f);
        g_doutdeg[v] = (float)g_cnt_src[v];
    }
}

// ---------------- double-buffered GEMM: C[M,BN] = A[M,128] @ W[128,BN] ----------------
// BM=128, BK=16, 256 threads, 8x(BN/16) register tile, 2-stage smem pipeline.
// act: 0 none, 1 tanh, 2 relu
template <int BN>
__global__ void __launch_bounds__(256, 2) k_gemm_db(
    const float* Aext, int aSel,
    const float* __restrict__ W,
    const float* __restrict__ bias,
    int useDis,
    float* Cext, int cSel,
    int act)
{
    const int TN = BN / 16;
    const int WL = BN / 64;               // W float4 loads per thread per tile
    const float* A = Aext ? Aext : buf_by_id(aSel);
    float* C = Cext ? Cext : buf_by_id(cSel);

    __shared__ float sA[2][16][132];      // transposed A tile (pad 132: mod32=4)
    __shared__ float sW[2][16][BN];

    int tid = threadIdx.x;
    int ty = tid >> 4, tx = tid & 15;
    int rb = blockIdx.x * 128;

    // load index precompute
    int ar[2], ac[2];
    #pragma unroll
    for (int i = 0; i < 2; i++) { int idx = tid + i * 256; ar[i] = idx >> 2; ac[i] = (idx & 3) << 2; }
    int wr[WL], wc[WL];
    #pragma unroll
    for (int i = 0; i < WL; i++) { int idx = tid + i * 256; wr[i] = idx / (BN / 4); wc[i] = (idx % (BN / 4)) << 2; }

    float4 pa[2], pw[WL];

    // prefetch tile 0
    #pragma unroll
    for (int i = 0; i < 2; i++)
        pa[i] = *reinterpret_cast<const float4*>(A + (size_t)(rb + ar[i]) * 128 + ac[i]);
    #pragma unroll
    for (int i = 0; i < WL; i++)
        pw[i] = *reinterpret_cast<const float4*>(W + (size_t)wr[i] * BN + wc[i]);
    #pragma unroll
    for (int i = 0; i < 2; i++) {
        sA[0][ac[i] + 0][ar[i]] = pa[i].x; sA[0][ac[i] + 1][ar[i]] = pa[i].y;
        sA[0][ac[i] + 2][ar[i]] = pa[i].z; sA[0][ac[i] + 3][ar[i]] = pa[i].w;
    }
    #pragma unroll
    for (int i = 0; i < WL; i++)
        *reinterpret_cast<float4*>(&sW[0][wr[i]][wc[i]]) = pw[i];
    __syncthreads();

    float acc[8][TN];
    #pragma unroll
    for (int i = 0; i < 8; i++)
        #pragma unroll
        for (int j = 0; j < TN; j++) acc[i][j] = 0.f;

    #pragma unroll
    for (int t = 0; t < 8; t++) {
        int buf = t & 1;
        if (t < 7) {
            int k0 = (t + 1) * 16;
            #pragma unroll
            for (int i = 0; i < 2; i++)
                pa[i] = *reinterpret_cast<const float4*>(A + (size_t)(rb + ar[i]) * 128 + k0 + ac[i]);
            #pragma unroll
            for (int i = 0; i < WL; i++)
                pw[i] = *reinterpret_cast<const float4*>(W + (size_t)(k0 + wr[i]) * BN + wc[i]);
        }
        #pragma unroll
        for (int kk = 0; kk < 16; kk++) {
            float a[8], b[TN];
            *reinterpret_cast<float4*>(&a[0]) = *reinterpret_cast<const float4*>(&sA[buf][kk][ty * 8]);
            *reinterpret_cast<float4*>(&a[4]) = *reinterpret_cast<const float4*>(&sA[buf][kk][ty * 8 + 4]);
            #pragma unroll
            for (int jg = 0; jg < TN / 4; jg++)
                *reinterpret_cast<float4*>(&b[jg * 4]) =
                    *reinterpret_cast<const float4*>(&sW[buf][kk][tx * TN + jg * 4]);
            #pragma unroll
            for (int i = 0; i < 8; i++)
                #pragma unroll
                for (int j = 0; j < TN; j++)
                    acc[i][j] = fmaf(a[i], b[j], acc[i][j]);
        }
        if (t < 7) {
            int nb = buf ^ 1;
            #pragma unroll
            for (int i = 0; i < 2; i++) {
                sA[nb][ac[i] + 0][ar[i]] = pa[i].x; sA[nb][ac[i] + 1][ar[i]] = pa[i].y;
                sA[nb][ac[i] + 2][ar[i]] = pa[i].z; sA[nb][ac[i] + 3][ar[i]] = pa[i].w;
            }
            #pragma unroll
            for (int i = 0; i < WL; i++)
                *reinterpret_cast<float4*>(&sW[nb][wr[i]][wc[i]]) = pw[i];
            __syncthreads();
        }
    }

    // epilogue
    float bb[TN];
    if (bias) {
        #pragma unroll
        for (int jg = 0; jg < TN / 4; jg++)
            *reinterpret_cast<float4*>(&bb[jg * 4]) =
                *reinterpret_cast<const float4*>(bias + tx * TN + jg * 4);
    }
    #pragma unroll
    for (int i = 0; i < 8; i++) {
        int row = rb + ty * 8 + i;
        float rs = useDis ? g_dis[row] : 1.0f;
        float o[TN];
        #pragma unroll
        for (int j = 0; j < TN; j++) {
            float v = acc[i][j];
            if (bias) v += bb[j];
            v *= rs;
            if (act == 1) v = tanhf(v);
            else if (act == 2) v = fmaxf(v, 0.f);
            o[j] = v;
        }
        #pragma unroll
        for (int jg = 0; jg < TN / 4; jg++)
            *reinterpret_cast<float4*>(C + (size_t)row * BN + tx * TN + jg * 4) =
                *reinterpret_cast<float4*>(&o[jg * 4]);
    }
}

// ---------------- small GEMM (BM=64) for the tiny pooled projection ----------------
template <int BN>
__global__ void __launch_bounds__(256) k_gemm(
    const float* Aext, int aSel,
    const float* __restrict__ W,
    const float* __restrict__ bias,
    int useDis,
    float* Cext, int cSel,
    int act)
{
    const int TN = BN / 16;
    const float* A = Aext ? Aext : buf_by_id(aSel);
    float* C = Cext ? Cext : buf_by_id(cSel);

    __shared__ float sA[32][68];
    __shared__ float sW[32][BN];

    int tid = threadIdx.x;
    int ty = tid >> 4, tx = tid & 15;
    int rb = blockIdx.x * 64;

    float acc[4][TN];
    #pragma unroll
    for (int i = 0; i < 4; i++)
        #pragma unroll
        for (int j = 0; j < TN; j++) acc[i][j] = 0.f;

    for (int k0 = 0; k0 < 128; k0 += 32) {
        #pragma unroll
        for (int i = 0; i < 2; i++) {
            int idx = tid + i * 256;
            int r = idx >> 3, c4 = (idx & 7) << 2;
            float4 v = *reinterpret_cast<const float4*>(A + (size_t)(rb + r) * 128 + k0 + c4);
            sA[c4 + 0][r] = v.x; sA[c4 + 1][r] = v.y;
            sA[c4 + 2][r] = v.z; sA[c4 + 3][r] = v.w;
        }
        #pragma unroll
        for (int i = 0; i < BN / 32; i++) {
            int idx = tid + i * 256;
            int r = idx / (BN / 4), c4 = (idx % (BN / 4)) << 2;
            *reinterpret_cast<float4*>(&sW[r][c4]) =
                *reinterpret_cast<const float4*>(W + (size_t)(k0 + r) * BN + c4);
        }
        __syncthreads();
        #pragma unroll
        for (int kk = 0; kk < 32; kk++) {
            float4 av = *reinterpret_cast<const float4*>(&sA[kk][ty * 4]);
            float a[4] = {av.x, av.y, av.z, av.w};
            float b[TN];
            #pragma unroll
            for (int jg = 0; jg < TN / 4; jg++) {
                float4 bv = *reinterpret_cast<const float4*>(&sW[kk][tx * TN + jg * 4]);
                b[jg * 4 + 0] = bv.x; b[jg * 4 + 1] = bv.y;
                b[jg * 4 + 2] = bv.z; b[jg * 4 + 3] = bv.w;
            }
            #pragma unroll
            for (int i = 0; i < 4; i++)
                #pragma unroll
                for (int j = 0; j < TN; j++)
                    acc[i][j] = fmaf(a[i], b[j], acc[i][j]);
        }
        __syncthreads();
    }

    #pragma unroll
    for (int i = 0; i < 4; i++) {
        int row = rb + ty * 4 + i;
        float rs = useDis ? g_dis[row] : 1.0f;
        #pragma unroll
        for (int j = 0; j < TN; j++) {
            int col = tx * TN + j;
            float v = acc[i][j];
            if (bias) v += bias[col];
            v *= rs;
            if (act == 1) v = tanhf(v);
            else if (act == 2) v = fmaxf(v, 0.f);
            C[(size_t)row * BN + col] = v;
        }
    }
}

// ---------------- GCN aggregation (F=128): warp per node, MLP-4 unrolled gather ----
__global__ void __launch_bounds__(256) k_agg_f128(const float* __restrict__ bias, int relu) {
    int w = (blockIdx.x * blockDim.x + threadIdx.x) >> 5;
    int lane = threadIdx.x & 31;
    if (w >= NN) return;
    const float* hh = g_bufA;
    float4 acc0 = *reinterpret_cast<const float4*>(hh + (size_t)w * 128 + lane * 4); // self loop
    float4 acc1 = make_float4(0.f, 0.f, 0.f, 0.f);
    float4 acc2 = make_float4(0.f, 0.f, 0.f, 0.f);
    float4 acc3 = make_float4(0.f, 0.f, 0.f, 0.f);
    int n = g_cnt_dst[w];
    const int* lst = g_adj_dst + (size_t)w * PAD;
    int e = 0;
    for (; e + 4 <= n; e += 4) {
        int u0 = __ldg(&lst[e]),     u1 = __ldg(&lst[e + 1]);
        int u2 = __ldg(&lst[e + 2]), u3 = __ldg(&lst[e + 3]);
        float4 v0 = *reinterpret_cast<const float4*>(hh + (size_t)u0 * 128 + lane * 4);
        float4 v1 = *reinterpret_cast<const float4*>(hh + (size_t)u1 * 128 + lane * 4);
        float4 v2 = *reinterpret_cast<const float4*>(hh + (size_t)u2 * 128 + lane * 4);
        float4 v3 = *reinterpret_cast<const float4*>(hh + (size_t)u3 * 128 + lane * 4);
        acc0.x += v0.x; acc0.y += v0.y; acc0.z += v0.z; acc0.w += v0.w;
        acc1.x += v1.x; acc1.y += v1.y; acc1.z += v1.z; acc1.w += v1.w;
        acc2.x += v2.x; acc2.y += v2.y; acc2.z += v2.z; acc2.w += v2.w;
        acc3.x += v3.x; acc3.y += v3.y; acc3.z += v3.z; acc3.w += v3.w;
    }
    for (; e < n; e++) {
        int u = __ldg(&lst[e]);
        float4 v = *reinterpret_cast<const float4*>(hh + (size_t)u * 128 + lane * 4);
        acc0.x += v.x; acc0.y += v.y; acc0.z += v.z; acc0.w += v.w;
    }
    acc0.x += acc1.x + acc2.x + acc3.x;
    acc0.y += acc1.y + acc2.y + acc3.y;
    acc0.z += acc1.z + acc2.z + acc3.z;
    acc0.w += acc1.w + acc2.w + acc3.w;
    float d = g_dis[w];
    float4 bb = *reinterpret_cast<const float4*>(bias + lane * 4);
    float4 r;
    r.x = acc0.x * d + bb.x; r.y = acc0.y * d + bb.y;
    r.z = acc0.z * d + bb.z; r.w = acc0.w * d + bb.w;
    if (relu) {
        r.x = fmaxf(r.x, 0.f); r.y = fmaxf(r.y, 0.f);
        r.z = fmaxf(r.z, 0.f); r.w = fmaxf(r.w, 0.f);
    }
    *reinterpret_cast<float4*>(g_bufB + (size_t)w * 128 + lane * 4) = r;
}

// ---------------- warp reductions ----------------
__device__ __forceinline__ float wredmax(float v) {
    #pragma unroll
    for (int o = 16; o; o >>= 1) v = fmaxf(v, __shfl_xor_sync(FULLM, v, o));
    return v;
}
__device__ __forceinline__ float wredsum(float v) {
    #pragma unroll
    for (int o = 16; o; o >>= 1) v += __shfl_xor_sync(FULLM, v, o);
    return v;
}

// ---------------- double softmax over K=64 (warp per node) + mincut_den partial ----
__global__ void __launch_bounds__(256) k_softmax() {
    int n = (blockIdx.x * blockDim.x + threadIdx.x) >> 5;
    int lane = threadIdx.x & 31;
    if (n >= NN) return;
    float2 z = *reinterpret_cast<const float2*>(g_s_buf + (size_t)n * 64 + lane * 2);
    float m = wredmax(fmaxf(z.x, z.y));
    float ex = expf(z.x - m), ey = expf(z.y - m);
    float s = wredsum(ex + ey);
    float px = ex / s, py = ey / s;
    float m2 = wredmax(fmaxf(px, py));
    float ex2 = expf(px - m2), ey2 = expf(py - m2);
    float s2 = wredsum(ex2 + ey2);
    float qx = ex2 / s2, qy = ey2 / s2;
    *reinterpret_cast<float2*>(g_s_buf + (size_t)n * 64 + lane * 2) = make_float2(qx, qy);
    float t = wredsum(qx * qx + qy * qy);
    if (lane == 0) atomicAdd(&g_den[n >> 12], g_doutdeg[n] * t);
}

// ---------------- As[u] = sum_{u->v} s_d[v]  (warp per node, MLP-4 unrolled) -------
__global__ void __launch_bounds__(256) k_agg_as() {
    int w = (blockIdx.x * blockDim.x + threadIdx.x) >> 5;
    int lane = threadIdx.x & 31;
    if (w >= NN) return;
    float2 a0 = make_float2(0.f, 0.f), a1 = make_float2(0.f, 0.f);
    float2 a2 = make_float2(0.f, 0.f), a3 = make_float2(0.f, 0.f);
    int n = g_cnt_src[w];
    const int* lst = g_adj_src + (size_t)w * PAD;
    int e = 0;
    for (; e + 4 <= n; e += 4) {
        int v0 = __ldg(&lst[e]),     v1 = __ldg(&lst[e + 1]);
        int v2 = __ldg(&lst[e + 2]), v3 = __ldg(&lst[e + 3]);
        float2 t0 = *reinterpret_cast<const float2*>(g_s_buf + (size_t)v0 * 64 + lane * 2);
        float2 t1 = *reinterpret_cast<const float2*>(g_s_buf + (size_t)v1 * 64 + lane * 2);
        float2 t2 = *reinterpret_cast<const float2*>(g_s_buf + (size_t)v2 * 64 + lane * 2);
        float2 t3 = *reinterpret_cast<const float2*>(g_s_buf + (size_t)v3 * 64 + lane * 2);
        a0.x += t0.x; a0.y += t0.y;
        a1.x += t1.x; a1.y += t1.y;
        a2.x += t2.x; a2.y += t2.y;
        a3.x += t3.x; a3.y += t3.y;
    }
    for (; e < n; e++) {
        int v = __ldg(&lst[e]);
        float2 t = *reinterpret_cast<const float2*>(g_s_buf + (size_t)v * 64 + lane * 2);
        a0.x += t.x; a0.y += t.y;
    }
    a0.x += a1.x + a2.x + a3.x;
    a0.y += a1.y + a2.y + a3.y;
    *reinterpret_cast<float2*>(g_As + (size_t)w * 64 + lane * 2) = a0;
}

// ---------------- fused pooling reductions -----------------------------------------
__global__ void __launch_bounds__(256) k_pool() {
    int b = blockIdx.x >> 5;
    int chunk = blockIdx.x & 31;
    int tid = threadIdx.x;
    int ty = tid >> 4, tx = tid & 15;

    __shared__ float s_t[16][64];
    __shared__ float a_t[16][64];
    __shared__ float h_t[16][128];

    float racc[4][4] = {}, sacc[4][4] = {}, oacc[4][8] = {};

    for (int t = 0; t < 8; t++) {
        int nbase = b * NPG + chunk * 128 + t * 16;
        {
            int r = tid >> 4, c4 = (tid & 15) << 2;
            *reinterpret_cast<float4*>(&s_t[r][c4]) =
                *reinterpret_cast<const float4*>(g_s_buf + (size_t)(nbase + r) * 64 + c4);
            *reinterpret_cast<float4*>(&a_t[r][c4]) =
                *reinterpret_cast<const float4*>(g_As + (size_t)(nbase + r) * 64 + c4);
        }
        #pragma unroll
        for (int i = 0; i < 2; i++) {
            int idx = tid + i * 256;
            int r = idx >> 5, c4 = (idx & 31) << 2;
            *reinterpret_cast<float4*>(&h_t[r][c4]) =
                *reinterpret_cast<const float4*>(g_bufB + (size_t)(nbase + r) * 128 + c4);
        }
        __syncthreads();
        #pragma unroll
        for (int n = 0; n < 16; n++) {
            float4 skv = *reinterpret_cast<const float4*>(&s_t[n][ty * 4]);
            float4 ajv = *reinterpret_cast<const float4*>(&a_t[n][tx * 4]);
            float4 sjv = *reinterpret_cast<const float4*>(&s_t[n][tx * 4]);
            float4 h0v = *reinterpret_cast<const float4*>(&h_t[n][tx * 8]);
            float4 h1v = *reinterpret_cast<const float4*>(&h_t[n][tx * 8 + 4]);
            float sk[4] = {skv.x, skv.y, skv.z, skv.w};
            float aj[4] = {ajv.x, ajv.y, ajv.z, ajv.w};
            float sj[4] = {sjv.x, sjv.y, sjv.z, sjv.w};
            float hf[8] = {h0v.x, h0v.y, h0v.z, h0v.w, h1v.x, h1v.y, h1v.z, h1v.w};
            #pragma unroll
            for (int i = 0; i < 4; i++) {
                #pragma unroll
                for (int j = 0; j < 4; j++) {
                    racc[i][j] = fmaf(sk[i], aj[j], racc[i][j]);
                    sacc[i][j] = fmaf(sk[i], sj[j], sacc[i][j]);
                }
                #pragma unroll
                for (int j = 0; j < 8; j++)
                    oacc[i][j] = fmaf(sk[i], hf[j], oacc[i][j]);
            }
        }
        __syncthreads();
    }

    #pragma unroll
    for (int i = 0; i < 4; i++) {
        int k = ty * 4 + i;
        #pragma unroll
        for (int j = 0; j < 4; j++) {
            int c = tx * 4 + j;
            atomicAdd(&g_outadj[b * 4096 + k * 64 + c], racc[i][j]);
            atomicAdd(&g_ssm[b * 4096 + k * 64 + c], sacc[i][j]);
        }
        #pragma unroll
        for (int j = 0; j < 8; j++) {
            int f = tx * 8 + j;
            atomicAdd(&g_out_pool[(size_t)(b * 64 + k) * 128 + f], oacc[i][j]);
        }
    }
}

// ---------------- per-graph finalize: losses + normalized out_adj ------------------
__device__ __forceinline__ float block_reduce256(float v, float* red) {
    int tid = threadIdx.x;
    red[tid] = v;
    __syncthreads();
    for (int s = 128; s > 0; s >>= 1) {
        if (tid < s) red[tid] += red[tid + s];
        __syncthreads();
    }
    float r = red[0];
    __syncthreads();
    return r;
}

__global__ void __launch_bounds__(256) k_finalize(float* __restrict__ out) {
    int b = blockIdx.x;
    int tid = threadIdx.x;
    __shared__ float oa[4096];
    __shared__ float red[256];
    __shared__ float dsh[64];

    for (int i = tid; i < 4096; i += 256) oa[i] = g_outadj[b * 4096 + i];
    __syncthreads();

    float tv = (tid < 64) ? oa[tid * 65] : 0.f;
    float trace = block_reduce256(tv, red);

    float s2 = 0.f;
    for (int i = tid; i < 4096; i += 256) {
        float v = g_ssm[b * 4096 + i];
        s2 += v * v;
    }
    float ssn = sqrtf(block_reduce256(s2, red));

    float o2 = 0.f;
    for (int i = tid; i < 4096; i += 256) {
        float v = g_ssm[b * 4096 + i] / ssn;
        if (i % 65 == 0) v -= 0.125f;   // 1/sqrt(64)
        o2 += v * v;
    }
    float ortho = sqrtf(block_reduce256(o2, red));

    if (tid < 64) {
        float rs = 0.f;
        for (int j = 0; j < 64; j++)
            if (j != tid) rs += oa[tid * 64 + j];
        dsh[tid] = sqrtf(rs) + 1e-15f;
    }
    __syncthreads();

    for (int i = tid; i < 4096; i += 256) {
        int k = i >> 6, j = i & 63;
        float v = (k == j) ? 0.f : oa[i] / (dsh[k] * dsh[j]);
        out[OA_OFF + b * 4096 + i] = v;
    }

    if (tid == 0) {
        g_mb[b] = -trace / g_den[b];
        g_ob[b] = ortho;
    }
}

// ---------------- scalars + pooled_batch -------------------------------------------
__global__ void k_scalars(float* __restrict__ out) {
    int tid = threadIdx.x;   // 512 threads
    out[PB_OFF + tid] = (float)(tid >> 6);
    if (tid == 0) {
        float m = 0.f, o = 0.f;
        for (int b = 0; b < NG; b++) { m += g_mb[b]; o += g_ob[b]; }
        out[ML_OFF] = m / (float)NG;
        out[OL_OFF] = o / (float)NG;
    }
}

// ---------------- launcher ----------------------------------------------------------
extern "C" void kernel_launch(void* const* d_in, const int* in_sizes, int n_in,
                              void* d_out, int out_size) {
    (void)in_sizes; (void)n_in; (void)out_size;
    const float* x   = (const float*)d_in[0];
    const int*   ei  = (const int*)d_in[1];
    const float* W1  = (const float*)d_in[3];
    const float* b1  = (const float*)d_in[4];
    const float* W2  = (const float*)d_in[5];
    const float* b2  = (const float*)d_in[6];
    const float* Wa1 = (const float*)d_in[7];
    const float* ba1 = (const float*)d_in[8];
    const float* Wa2 = (const float*)d_in[9];
    const float* ba2 = (const float*)d_in[10];
    const float* Wo  = (const float*)d_in[11];
    const float* bo  = (const float*)d_in[12];
    float* out = (float*)d_out;
    const int* src = ei;
    const int* dst = ei + NE;

    k_zero<<<256, 256>>>();
    k_scatter<<<512, 256>>>(src, dst);
    k_dis<<<128, 256>>>();

    // GCN layer 1: hh = (x @ W1) * dis -> bufA ; h1 = relu((agg+self)*dis + b1) -> bufB
    k_gemm_db<128><<<NN / 128, 256>>>(x, -1, W1, nullptr, 1, nullptr, 0, 0);
    k_agg_f128<<<NN / 8, 256>>>(b1, 1);

    // GCN layer 2
    k_gemm_db<128><<<NN / 128, 256>>>(nullptr, 1, W2, nullptr, 1, nullptr, 0, 0);
    k_agg_f128<<<NN / 8, 256>>>(b2, 0);

    // assignment MLP: a = tanh(h2 @ Wa1 + ba1) -> bufA ; logits = a @ Wa2 + ba2 -> g_s
    k_gemm_db<128><<<NN / 128, 256>>>(nullptr, 1, Wa1, ba1, 0, nullptr, 0, 1);
    k_gemm_db<64><<<NN / 128, 256>>>(nullptr, 0, Wa2, ba2, 0, nullptr, 2, 0);

    // double softmax (+ mincut_den), As = A @ s_d
    k_softmax<<<NN / 8, 256>>>();
    k_agg_as<<<NN / 8, 256>>>();

    // fused pooled reductions: out_adj, ss, out_pool
    k_pool<<<NG * 32, 256>>>();

    // pooled_x = relu(out_pool @ Wo + bo) -> out[0:65536]
    k_gemm<128><<<(NG * KD) / 64, 256>>>(nullptr, 3, Wo, bo, 0, out, -1, 2);

    k_finalize<<<NG, 256>>>(out);
    k_scalars<<<1, 512>>>(out);
}

// round 10
// speedup vs baseline: 1.0246x; 1.0246x over previous
#include <cuda_runtime.h>

// ---------------- problem constants ----------------
#define NN   32768      // total nodes (B*N)
#define NG   8          // graphs
#define NPG  4096       // nodes per graph
#define NE   524288     // total edges
#define FD   128        // feature dim
#define KD   64         // clusters
#define PAD  128        // adjacency slot pad (max degree << 128, Poisson(16))

// output layout (flat float32)
#define PX_OFF 0        // pooled_x   [512*128]
#define OA_OFF 65536    // out_adj    [8*64*64]
#define PB_OFF 98304    // pooled_batch [512]
#define ML_OFF 98816    // mincut_loss
#define OL_OFF 98817    // ortho_loss

#define FULLM 0xffffffffu

// ---------------- device scratch (static, no allocs) ----------------
static __device__ __align__(16) float g_bufA[NN * FD];      // 16 MB
static __device__ __align__(16) float g_bufB[NN * FD];      // 16 MB
static __device__ __align__(16) float g_s_buf[NN * KD];     // 8 MB  (logits -> s_d)
static __device__ __align__(16) float g_As[NN * KD];        // 8 MB
static __device__ __align__(16) float g_out_pool[NG * KD * FD];
static __device__ float g_outadj[NG * KD * KD];
static __device__ float g_ssm[NG * KD * KD];
static __device__ float g_den[NG];
static __device__ float g_mb[NG];
static __device__ float g_ob[NG];
static __device__ float g_dis[NN];
static __device__ float g_doutdeg[NN];
static __device__ int   g_cnt_dst[NN];
static __device__ int   g_cnt_src[NN];
static __device__ int   g_adj_dst[NN * PAD];   // 16 MB
static __device__ int   g_adj_src[NN * PAD];   // 16 MB

__device__ __forceinline__ float* buf_by_id(int id) {
    switch (id) {
        case 0: return g_bufA;
        case 1: return g_bufB;
        case 2: return g_s_buf;
        default: return g_out_pool;
    }
}

// ---------------- cp.async helpers ----------------
__device__ __forceinline__ void cp_async16(void* smem_dst, const void* gmem_src) {
    unsigned saddr = (unsigned)__cvta_generic_to_shared(smem_dst);
    asm volatile("cp.async.cg.shared.global [%0], [%1], 16;\n" :: "r"(saddr), "l"(gmem_src));
}
__device__ __forceinline__ void cp_commit() {
    asm volatile("cp.async.commit_group;\n");
}
template <int N>
__device__ __forceinline__ void cp_wait() {
    asm volatile("cp.async.wait_group %0;\n" :: "n"(N));
}

// ---------------- zero scratch ----------------
__global__ void k_zero() {
    int i = blockIdx.x * blockDim.x + threadIdx.x;   // 65536 threads
    if (i < NN) {
        g_cnt_dst[i] = 0; g_cnt_src[i] = 0;
        g_outadj[i] = 0.f; g_ssm[i] = 0.f;           // NG*KD*KD == NN
    }
    g_out_pool[i] = 0.f;                             // exactly 65536
    if (i < NG) g_den[i] = 0.f;
}

// ---------------- adjacency build: no histogram, no scan ----------------
__global__ void k_scatter(const int* __restrict__ src, const int* __restrict__ dst) {
    int idx = blockIdx.x * blockDim.x + threadIdx.x;
    int stride = gridDim.x * blockDim.x;
    for (int e = idx; e < NE; e += stride) {
        int s = src[e], d = dst[e];
        int pd = atomicAdd(&g_cnt_dst[d], 1);
        if (pd < PAD) g_adj_dst[d * PAD + pd] = s;
        int ps = atomicAdd(&g_cnt_src[s], 1);
        if (ps < PAD) g_adj_src[s * PAD + ps] = d;
    }
}

// ---------------- dis = rsqrt(indeg+1), doutdeg = outdeg ----------------
__global__ void k_dis() {
    int v = blockIdx.x * blockDim.x + threadIdx.x;
    if (v < NN) {
        g_dis[v] = rsqrtf((float)g_cnt_dst[v] + 1.0f);
        g_doutdeg[v] = (float)g_cnt_src[v];
    }
}

// ---------------- cp.async pipelined GEMM: C[M,BN] = A[M,128] @ W[128,BN] ----------
// BM=128, BK=16, 256 threads, 8x(BN/16) register tile. A kept row-major in smem
// (scalar broadcast reads); tiles stream via cp.async double buffering.
// act: 0 none, 1 tanh, 2 relu
template <int BN>
__global__ void __launch_bounds__(256, 2) k_gemm_cp(
    const float* Aext, int aSel,
    const float* __restrict__ W,
    const float* __restrict__ bias,
    int useDis,
    float* Cext, int cSel,
    int act)
{
    const int TN = BN / 16;
    const int WL = BN / 64;               // 16B W chunks per thread per tile
    const float* A = Aext ? Aext : buf_by_id(aSel);
    float* C = Cext ? Cext : buf_by_id(cSel);

    __shared__ float sA[2][128][20];      // row-major A tile, 16 valid cols, 16B-aligned rows
    __shared__ float sW[2][16][BN];

    int tid = threadIdx.x;
    int ty = tid >> 4, tx = tid & 15;
    int rb = blockIdx.x * 128;

    // load index precompute: A tile = 512 16B-chunks (2/thread), W tile = 256*WL
    int ar[2], ac[2];
    #pragma unroll
    for (int i = 0; i < 2; i++) { int idx = tid + i * 256; ar[i] = idx >> 2; ac[i] = (idx & 3) << 2; }
    int wr[WL], wc[WL];
    #pragma unroll
    for (int i = 0; i < WL; i++) { int idx = tid + i * 256; wr[i] = idx / (BN / 4); wc[i] = (idx % (BN / 4)) << 2; }

    // prefetch tile 0
    #pragma unroll
    for (int i = 0; i < 2; i++)
        cp_async16(&sA[0][ar[i]][ac[i]], A + (size_t)(rb + ar[i]) * 128 + ac[i]);
    #pragma unroll
    for (int i = 0; i < WL; i++)
        cp_async16(&sW[0][wr[i]][wc[i]], W + (size_t)wr[i] * BN + wc[i]);
    cp_commit();

    float acc[8][TN];
    #pragma unroll
    for (int i = 0; i < 8; i++)
        #pragma unroll
        for (int j = 0; j < TN; j++) acc[i][j] = 0.f;

    #pragma unroll 2
    for (int t = 0; t < 8; t++) {
        int buf = t & 1;
        if (t < 7) {
            int k0 = (t + 1) * 16;
            int nb = buf ^ 1;
            #pragma unroll
            for (int i = 0; i < 2; i++)
                cp_async16(&sA[nb][ar[i]][ac[i]], A + (size_t)(rb + ar[i]) * 128 + k0 + ac[i]);
            #pragma unroll
            for (int i = 0; i < WL; i++)
                cp_async16(&sW[nb][wr[i]][wc[i]], W + (size_t)(k0 + wr[i]) * BN + wc[i]);
            cp_commit();
            cp_wait<1>();     // tile t resident, tile t+1 in flight
        } else {
            cp_wait<0>();
        }
        __syncthreads();
        #pragma unroll
        for (int kk = 0; kk < 16; kk++) {
            float a[8], b[TN];
            #pragma unroll
            for (int i = 0; i < 8; i++) a[i] = sA[buf][ty * 8 + i][kk];   // broadcast LDS
            #pragma unroll
            for (int jg = 0; jg < TN / 4; jg++)
                *reinterpret_cast<float4*>(&b[jg * 4]) =
                    *reinterpret_cast<const float4*>(&sW[buf][kk][tx * TN + jg * 4]);
            #pragma unroll
            for (int i = 0; i < 8; i++)
                #pragma unroll
                for (int j = 0; j < TN; j++)
                    acc[i][j] = fmaf(a[i], b[j], acc[i][j]);
        }
        __syncthreads();      // protect buf from next iteration's cp.async writes
    }

    // epilogue
    float bb[TN];
    if (bias) {
        #pragma unroll
        for (int jg = 0; jg < TN / 4; jg++)
            *reinterpret_cast<float4*>(&bb[jg * 4]) =
                *reinterpret_cast<const float4*>(bias + tx * TN + jg * 4);
    }
    #pragma unroll
    for (int i = 0; i < 8; i++) {
        int row = rb + ty * 8 + i;
        float rs = useDis ? g_dis[row] : 1.0f;
        float o[TN];
        #pragma unroll
        for (int j = 0; j < TN; j++) {
            float v = acc[i][j];
            if (bias) v += bb[j];
            v *= rs;
            if (act == 1) v = tanhf(v);
            else if (act == 2) v = fmaxf(v, 0.f);
            o[j] = v;
        }
        #pragma unroll
        for (int jg = 0; jg < TN / 4; jg++)
            *reinterpret_cast<float4*>(C + (size_t)row * BN + tx * TN + jg * 4) =
                *reinterpret_cast<float4*>(&o[jg * 4]);
    }
}

// ---------------- small GEMM (BM=64) for the tiny pooled projection ----------------
template <int BN>
__global__ void __launch_bounds__(256) k_gemm(
    const float* Aext, int aSel,
    const float* __restrict__ W,
    const float* __restrict__ bias,
    int useDis,
    float* Cext, int cSel,
    int act)
{
    const int TN = BN / 16;
    const float* A = Aext ? Aext : buf_by_id(aSel);
    float* C = Cext ? Cext : buf_by_id(cSel);

    __shared__ float sA[32][68];
    __shared__ float sW[32][BN];

    int tid = threadIdx.x;
    int ty = tid >> 4, tx = tid & 15;
    int rb = blockIdx.x * 64;

    float acc[4][TN];
    #pragma unroll
    for (int i = 0; i < 4; i++)
        #pragma unroll
        for (int j = 0; j < TN; j++) acc[i][j] = 0.f;

    for (int k0 = 0; k0 < 128; k0 += 32) {
        #pragma unroll
        for (int i = 0; i < 2; i++) {
            int idx = tid + i * 256;
            int r = idx >> 3, c4 = (idx & 7) << 2;
            float4 v = *reinterpret_cast<const float4*>(A + (size_t)(rb + r) * 128 + k0 + c4);
            sA[c4 + 0][r] = v.x; sA[c4 + 1][r] = v.y;
            sA[c4 + 2][r] = v.z; sA[c4 + 3][r] = v.w;
        }
        #pragma unroll
        for (int i = 0; i < BN / 32; i++) {
            int idx = tid + i * 256;
            int r = idx / (BN / 4), c4 = (idx % (BN / 4)) << 2;
            *reinterpret_cast<float4*>(&sW[r][c4]) =
                *reinterpret_cast<const float4*>(W + (size_t)(k0 + r) * BN + c4);
        }
        __syncthreads();
        #pragma unroll
        for (int kk = 0; kk < 32; kk++) {
            float4 av = *reinterpret_cast<const float4*>(&sA[kk][ty * 4]);
            float a[4] = {av.x, av.y, av.z, av.w};
            float b[TN];
            #pragma unroll
            for (int jg = 0; jg < TN / 4; jg++) {
                float4 bv = *reinterpret_cast<const float4*>(&sW[kk][tx * TN + jg * 4]);
                b[jg * 4 + 0] = bv.x; b[jg * 4 + 1] = bv.y;
                b[jg * 4 + 2] = bv.z; b[jg * 4 + 3] = bv.w;
            }
            #pragma unroll
            for (int i = 0; i < 4; i++)
                #pragma unroll
                for (int j = 0; j < TN; j++)
                    acc[i][j] = fmaf(a[i], b[j], acc[i][j]);
        }
        __syncthreads();
    }

    #pragma unroll
    for (int i = 0; i < 4; i++) {
        int row = rb + ty * 4 + i;
        float rs = useDis ? g_dis[row] : 1.0f;
        #pragma unroll
        for (int j = 0; j < TN; j++) {
            int col = tx * TN + j;
            float v = acc[i][j];
            if (bias) v += bias[col];
            v *= rs;
            if (act == 1) v = tanhf(v);
            else if (act == 2) v = fmaxf(v, 0.f);
            C[(size_t)row * BN + col] = v;
        }
    }
}

// ---------------- GCN aggregation (F=128): warp per node, MLP-4 unrolled gather ----
__global__ void __launch_bounds__(256) k_agg_f128(const float* __restrict__ bias, int relu) {
    int w = (blockIdx.x * blockDim.x + threadIdx.x) >> 5;
    int lane = threadIdx.x & 31;
    if (w >= NN) return;
    const float* hh = g_bufA;
    float4 acc0 = *reinterpret_cast<const float4*>(hh + (size_t)w * 128 + lane * 4); // self loop
    float4 acc1 = make_float4(0.f, 0.f, 0.f, 0.f);
    float4 acc2 = make_float4(0.f, 0.f, 0.f, 0.f);
    float4 acc3 = make_float4(0.f, 0.f, 0.f, 0.f);
    int n = g_cnt_dst[w];
    const int* lst = g_adj_dst + (size_t)w * PAD;
    int e = 0;
    for (; e + 4 <= n; e += 4) {
        int u0 = __ldg(&lst[e]),     u1 = __ldg(&lst[e + 1]);
        int u2 = __ldg(&lst[e + 2]), u3 = __ldg(&lst[e + 3]);
        float4 v0 = *reinterpret_cast<const float4*>(hh + (size_t)u0 * 128 + lane * 4);
        float4 v1 = *reinterpret_cast<const float4*>(hh + (size_t)u1 * 128 + lane * 4);
        float4 v2 = *reinterpret_cast<const float4*>(hh + (size_t)u2 * 128 + lane * 4);
        float4 v3 = *reinterpret_cast<const float4*>(hh + (size_t)u3 * 128 + lane * 4);
        acc0.x += v0.x; acc0.y += v0.y; acc0.z += v0.z; acc0.w += v0.w;
        acc1.x += v1.x; acc1.y += v1.y; acc1.z += v1.z; acc1.w += v1.w;
        acc2.x += v2.x; acc2.y += v2.y; acc2.z += v2.z; acc2.w += v2.w;
        acc3.x += v3.x; acc3.y += v3.y; acc3.z += v3.z; acc3.w += v3.w;
    }
    for (; e < n; e++) {
        int u = __ldg(&lst[e]);
        float4 v = *reinterpret_cast<const float4*>(hh + (size_t)u * 128 + lane * 4);
        acc0.x += v.x; acc0.y += v.y; acc0.z += v.z; acc0.w += v.w;
    }
    acc0.x += acc1.x + acc2.x + acc3.x;
    acc0.y += acc1.y + acc2.y + acc3.y;
    acc0.z += acc1.z + acc2.z + acc3.z;
    acc0.w += acc1.w + acc2.w + acc3.w;
    float d = g_dis[w];
    float4 bb = *reinterpret_cast<const float4*>(bias + lane * 4);
    float4 r;
    r.x = acc0.x * d + bb.x; r.y = acc0.y * d + bb.y;
    r.z = acc0.z * d + bb.z; r.w = acc0.w * d + bb.w;
    if (relu) {
        r.x = fmaxf(r.x, 0.f); r.y = fmaxf(r.y, 0.f);
        r.z = fmaxf(r.z, 0.f); r.w = fmaxf(r.w, 0.f);
    }
    *reinterpret_cast<float4*>(g_bufB + (size_t)w * 128 + lane * 4) = r;
}

// ---------------- warp reductions ----------------
__device__ __forceinline__ float wredmax(float v) {
    #pragma unroll
    for (int o = 16; o; o >>= 1) v = fmaxf(v, __shfl_xor_sync(FULLM, v, o));
    return v;
}
__device__ __forceinline__ float wredsum(float v) {
    #pragma unroll
    for (int o = 16; o; o >>= 1) v += __shfl_xor_sync(FULLM, v, o);
    return v;
}

// ---------------- double softmax over K=64 (warp per node) + mincut_den partial ----
__global__ void __launch_bounds__(256) k_softmax() {
    int n = (blockIdx.x * blockDim.x + threadIdx.x) >> 5;
    int lane = threadIdx.x & 31;
    if (n >= NN) return;
    float2 z = *reinterpret_cast<const float2*>(g_s_buf + (size_t)n * 64 + lane * 2);
    float m = wredmax(fmaxf(z.x, z.y));
    float ex = expf(z.x - m), ey = expf(z.y - m);
    float s = wredsum(ex + ey);
    float px = ex / s, py = ey / s;
    float m2 = wredmax(fmaxf(px, py));
    float ex2 = expf(px - m2), ey2 = expf(py - m2);
    float s2 = wredsum(ex2 + ey2);
    float qx = ex2 / s2, qy = ey2 / s2;
    *reinterpret_cast<float2*>(g_s_buf + (size_t)n * 64 + lane * 2) = make_float2(qx, qy);
    float t = wredsum(qx * qx + qy * qy);
    if (lane == 0) atomicAdd(&g_den[n >> 12], g_doutdeg[n] * t);
}

// ---------------- As[u] = sum_{u->v} s_d[v]  (warp per node, MLP-4 unrolled) -------
__global__ void __launch_bounds__(256) k_agg_as() {
    int w = (blockIdx.x * blockDim.x + threadIdx.x) >> 5;
    int lane = threadIdx.x & 31;
    if (w >= NN) return;
    float2 a0 = make_float2(0.f, 0.f), a1 = make_float2(0.f, 0.f);
    float2 a2 = make_float2(0.f, 0.f), a3 = make_float2(0.f, 0.f);
    int n = g_cnt_src[w];
    const int* lst = g_adj_src + (size_t)w * PAD;
    int e = 0;
    for (; e + 4 <= n; e += 4) {
        int v0 = __ldg(&lst[e]),     v1 = __ldg(&lst[e + 1]);
        int v2 = __ldg(&lst[e + 2]), v3 = __ldg(&lst[e + 3]);
        float2 t0 = *reinterpret_cast<const float2*>(g_s_buf + (size_t)v0 * 64 + lane * 2);
        float2 t1 = *reinterpret_cast<const float2*>(g_s_buf + (size_t)v1 * 64 + lane * 2);
        float2 t2 = *reinterpret_cast<const float2*>(g_s_buf + (size_t)v2 * 64 + lane * 2);
        float2 t3 = *reinterpret_cast<const float2*>(g_s_buf + (size_t)v3 * 64 + lane * 2);
        a0.x += t0.x; a0.y += t0.y;
        a1.x += t1.x; a1.y += t1.y;
        a2.x += t2.x; a2.y += t2.y;
        a3.x += t3.x; a3.y += t3.y;
    }
    for (; e < n; e++) {
        int v = __ldg(&lst[e]);
        float2 t = *reinterpret_cast<const float2*>(g_s_buf + (size_t)v * 64 + lane * 2);
        a0.x += t.x; a0.y += t.y;
    }
    a0.x += a1.x + a2.x + a3.x;
    a0.y += a1.y + a2.y + a3.y;
    *reinterpret_cast<float2*>(g_As + (size_t)w * 64 + lane * 2) = a0;
}

// ---------------- fused pooling reductions -----------------------------------------
__global__ void __launch_bounds__(256) k_pool() {
    int b = blockIdx.x >> 5;
    int chunk = blockIdx.x & 31;
    int tid = threadIdx.x;
    int ty = tid >> 4, tx = tid & 15;

    __shared__ float s_t[16][64];
    __shared__ float a_t[16][64];
    __shared__ float h_t[16][128];

    float racc[4][4] = {}, sacc[4][4] = {}, oacc[4][8] = {};

    for (int t = 0; t < 8; t++) {
        int nbase = b * NPG + chunk * 128 + t * 16;
        {
            int r = tid >> 4, c4 = (tid & 15) << 2;
            *reinterpret_cast<float4*>(&s_t[r][c4]) =
                *reinterpret_cast<const float4*>(g_s_buf + (size_t)(nbase + r) * 64 + c4);
            *reinterpret_cast<float4*>(&a_t[r][c4]) =
                *reinterpret_cast<const float4*>(g_As + (size_t)(nbase + r) * 64 + c4);
        }
        #pragma unroll
        for (int i = 0; i < 2; i++) {
            int idx = tid + i * 256;
            int r = idx >> 5, c4 = (idx & 31) << 2;
            *reinterpret_cast<float4*>(&h_t[r][c4]) =
                *reinterpret_cast<const float4*>(g_bufB + (size_t)(nbase + r) * 128 + c4);
        }
        __syncthreads();
        #pragma unroll
        for (int n = 0; n < 16; n++) {
            float4 skv = *reinterpret_cast<const float4*>(&s_t[n][ty * 4]);
            float4 ajv = *reinterpret_cast<const float4*>(&a_t[n][tx * 4]);
            float4 sjv = *reinterpret_cast<const float4*>(&s_t[n][tx * 4]);
            float4 h0v = *reinterpret_cast<const float4*>(&h_t[n][tx * 8]);
            float4 h1v = *reinterpret_cast<const float4*>(&h_t[n][tx * 8 + 4]);
            float sk[4] = {skv.x, skv.y, skv.z, skv.w};
            float aj[4] = {ajv.x, ajv.y, ajv.z, ajv.w};
            float sj[4] = {sjv.x, sjv.y, sjv.z, sjv.w};
            float hf[8] = {h0v.x, h0v.y, h0v.z, h0v.w, h1v.x, h1v.y, h1v.z, h1v.w};
            #pragma unroll
            for (int i = 0; i < 4; i++) {
                #pragma unroll
                for (int j = 0; j < 4; j++) {
                    racc[i][j] = fmaf(sk[i], aj[j], racc[i][j]);
                    sacc[i][j] = fmaf(sk[i], sj[j], sacc[i][j]);
                }
                #pragma unroll
                for (int j = 0; j < 8; j++)
                    oacc[i][j] = fmaf(sk[i], hf[j], oacc[i][j]);
            }
        }
        __syncthreads();
    }

    #pragma unroll
    for (int i = 0; i < 4; i++) {
        int k = ty * 4 + i;
        #pragma unroll
        for (int j = 0; j < 4; j++) {
            int c = tx * 4 + j;
            atomicAdd(&g_outadj[b * 4096 + k * 64 + c], racc[i][j]);
            atomicAdd(&g_ssm[b * 4096 + k * 64 + c], sacc[i][j]);
        }
        #pragma unroll
        for (int j = 0; j < 8; j++) {
            int f = tx * 8 + j;
            atomicAdd(&g_out_pool[(size_t)(b * 64 + k) * 128 + f], oacc[i][j]);
        }
    }
}

// ---------------- per-graph finalize: losses + normalized out_adj ------------------
__device__ __forceinline__ float block_reduce256(float v, float* red) {
    int tid = threadIdx.x;
    red[tid] = v;
    __syncthreads();
    for (int s = 128; s > 0; s >>= 1) {
        if (tid < s) red[tid] += red[tid + s];
        __syncthreads();
    }
    float r = red[0];
    __syncthreads();
    return r;
}

__global__ void __launch_bounds__(256) k_finalize(float* __restrict__ out) {
    int b = blockIdx.x;
    int tid = threadIdx.x;
    __shared__ float oa[4096];
    __shared__ float red[256];
    __shared__ float dsh[64];

    for (int i = tid; i < 4096; i += 256) oa[i] = g_outadj[b * 4096 + i];
    __syncthreads();

    float tv = (tid < 64) ? oa[tid * 65] : 0.f;
    float trace = block_reduce256(tv, red);

    float s2 = 0.f;
    for (int i = tid; i < 4096; i += 256) {
        float v = g_ssm[b * 4096 + i];
        s2 += v * v;
    }
    float ssn = sqrtf(block_reduce256(s2, red));

    float o2 = 0.f;
    for (int i = tid; i < 4096; i += 256) {
        float v = g_ssm[b * 4096 + i] / ssn;
        if (i % 65 == 0) v -= 0.125f;   // 1/sqrt(64)
        o2 += v * v;
    }
    float ortho = sqrtf(block_reduce256(o2, red));

    if (tid < 64) {
        float rs = 0.f;
        for (int j = 0; j < 64; j++)
            if (j != tid) rs += oa[tid * 64 + j];
        dsh[tid] = sqrtf(rs) + 1e-15f;
    }
    __syncthreads();

    for (int i = tid; i < 4096; i += 256) {
        int k = i >> 6, j = i & 63;
        float v = (k == j) ? 0.f : oa[i] / (dsh[k] * dsh[j]);
        out[OA_OFF + b * 4096 + i] = v;
    }

    if (tid == 0) {
        g_mb[b] = -trace / g_den[b];
        g_ob[b] = ortho;
    }
}

// ---------------- scalars + pooled_batch -------------------------------------------
__global__ void k_scalars(float* __restrict__ out) {
    int tid = threadIdx.x;   // 512 threads
    out[PB_OFF + tid] = (float)(tid >> 6);
    if (tid == 0) {
        float m = 0.f, o = 0.f;
        for (int b = 0; b < NG; b++) { m += g_mb[b]; o += g_ob[b]; }
        out[ML_OFF] = m / (float)NG;
        out[OL_OFF] = o / (float)NG;
    }
}

// ---------------- launcher ----------------------------------------------------------
extern "C" void kernel_launch(void* const* d_in, const int* in_sizes, int n_in,
                              void* d_out, int out_size) {
    (void)in_sizes; (void)n_in; (void)out_size;
    const float* x   = (const float*)d_in[0];
    const int*   ei  = (const int*)d_in[1];
    const float* W1  = (const float*)d_in[3];
    const float* b1  = (const float*)d_in[4];
    const float* W2  = (const float*)d_in[5];
    const float* b2  = (const float*)d_in[6];
    const float* Wa1 = (const float*)d_in[7];
    const float* ba1 = (const float*)d_in[8];
    const float* Wa2 = (const float*)d_in[9];
    const float* ba2 = (const float*)d_in[10];
    const float* Wo  = (const float*)d_in[11];
    const float* bo  = (const float*)d_in[12];
    float* out = (float*)d_out;
    const int* src = ei;
    const int* dst = ei + NE;

    k_zero<<<256, 256>>>();
    k_scatter<<<512, 256>>>(src, dst);
    k_dis<<<128, 256>>>();

    // GCN layer 1: hh = (x @ W1) * dis -> bufA ; h1 = relu((agg+self)*dis + b1) -> bufB
    k_gemm_cp<128><<<NN / 128, 256>>>(x, -1, W1, nullptr, 1, nullptr, 0, 0);
    k_agg_f128<<<NN / 8, 256>>>(b1, 1);

    // GCN layer 2
    k_gemm_cp<128><<<NN / 128, 256>>>(nullptr, 1, W2, nullptr, 1, nullptr, 0, 0);
    k_agg_f128<<<NN / 8, 256>>>(b2, 0);

    // assignment MLP: a = tanh(h2 @ Wa1 + ba1) -> bufA ; logits = a @ Wa2 + ba2 -> g_s
    k_gemm_cp<128><<<NN / 128, 256>>>(nullptr, 1, Wa1, ba1, 0, nullptr, 0, 1);
    k_gemm_cp<64><<<NN / 128, 256>>>(nullptr, 0, Wa2, ba2, 0, nullptr, 2, 0);

    // double softmax (+ mincut_den), As = A @ s_d
    k_softmax<<<NN / 8, 256>>>();
    k_agg_as<<<NN / 8, 256>>>();

    // fused pooled reductions: out_adj, ss, out_pool
    k_pool<<<NG * 32, 256>>>();

    // pooled_x = relu(out_pool @ Wo + bo) -> out[0:65536]
    k_gemm<128><<<(NG * KD) / 64, 256>>>(nullptr, 3, Wo, bo, 0, out, -1, 2);

    k_finalize<<<NG, 256>>>(out);
    k_scalars<<<1, 512>>>(out);
}

// round 12
// speedup vs baseline: 1.0552x; 1.0299x over previous
#include <cuda_runtime.h>
#include <cuda_bf16.h>
#include <stdint.h>

// ---------------- problem constants ----------------
#define NN   32768
#define NG   8
#define NPG  4096
#define NE   524288
#define FD   128
#define KD   64
#define PAD  128

#define PX_OFF 0
#define OA_OFF 65536
#define PB_OFF 98304
#define ML_OFF 98816
#define OL_OFF 98817

#define FULLM 0xffffffffu

// ---------------- device scratch ----------------
static __device__ __align__(16) float g_bufA[NN * FD];
static __device__ __align__(16) float g_bufB[NN * FD];
static __device__ __align__(16) float g_s_buf[NN * KD];
static __device__ __align__(16) float g_As[NN * KD];
static __device__ __align__(16) float g_out_pool[NG * KD * FD];
static __device__ float g_outadj[NG * KD * KD];
static __device__ float g_ssm[NG * KD * KD];
static __device__ float g_den[NG];
static __device__ float g_mb[NG];
static __device__ float g_ob[NG];
static __device__ float g_dis[NN];
static __device__ float g_doutdeg[NN];
static __device__ int   g_cnt_dst[NN];
static __device__ int   g_cnt_src[NN];
static __device__ int   g_adj_dst[NN * PAD];
static __device__ int   g_adj_src[NN * PAD];
// bf16 hi/lo weight images, [n][k] row-major (n rows of 128 k)
static __device__ __align__(16) __nv_bfloat16 g_wh1[16384], g_wl1[16384];
static __device__ __align__(16) __nv_bfloat16 g_wh2[16384], g_wl2[16384];
static __device__ __align__(16) __nv_bfloat16 g_wha1[16384], g_wla1[16384];
static __device__ __align__(16) __nv_bfloat16 g_wha2[8192],  g_wla2[8192];

__device__ __forceinline__ float* buf_by_id(int id) {
    switch (id) {
        case 0: return g_bufA;
        case 1: return g_bufB;
        case 2: return g_s_buf;
        default: return g_out_pool;
    }
}
__device__ __forceinline__ __nv_bfloat16* wimg(int which, int lo) {
    switch (which) {
        case 0: return lo ? g_wl1 : g_wh1;
        case 1: return lo ? g_wl2 : g_wh2;
        case 2: return lo ? g_wla1 : g_wha1;
        default: return lo ? g_wla2 : g_wha2;
    }
}

// ---------------- async helpers ----------------
__device__ __forceinline__ void cp_async16(void* smem_dst, const void* gmem_src) {
    unsigned saddr = (unsigned)__cvta_generic_to_shared(smem_dst);
    asm volatile("cp.async.cg.shared.global [%0], [%1], 16;\n" :: "r"(saddr), "l"(gmem_src));
}
__device__ __forceinline__ void cp_commit() { asm volatile("cp.async.commit_group;\n"); }
template <int N>
__device__ __forceinline__ void cp_wait() { asm volatile("cp.async.wait_group %0;\n" :: "n"(N)); }

__device__ __forceinline__ void hilo2(float a, float b, uint32_t& h, uint32_t& l) {
    __nv_bfloat162 hh = __floats2bfloat162_rn(a, b);
    __nv_bfloat162 ll = __floats2bfloat162_rn(a - __bfloat162float(hh.x),
                                              b - __bfloat162float(hh.y));
    h = *reinterpret_cast<uint32_t*>(&hh);
    l = *reinterpret_cast<uint32_t*>(&ll);
}

__device__ __forceinline__ void mma16816(float* d,
                                         uint32_t a0, uint32_t a1, uint32_t a2, uint32_t a3,
                                         uint32_t b0, uint32_t b1) {
    asm volatile(
        "mma.sync.aligned.m16n8k16.row.col.f32.bf16.bf16.f32 "
        "{%0,%1,%2,%3}, {%4,%5,%6,%7}, {%8,%9}, {%0,%1,%2,%3};"
        : "+f"(d[0]), "+f"(d[1]), "+f"(d[2]), "+f"(d[3])
        : "r"(a0), "r"(a1), "r"(a2), "r"(a3), "r"(b0), "r"(b1));
}

// ---------------- zero scratch ----------------
__global__ void k_zero() {
    int i = blockIdx.x * blockDim.x + threadIdx.x;
    if (i < NN) {
        g_cnt_dst[i] = 0; g_cnt_src[i] = 0;
        g_outadj[i] = 0.f; g_ssm[i] = 0.f;
    }
    g_out_pool[i] = 0.f;
    if (i < NG) g_den[i] = 0.f;
}

// ---------------- adjacency build ----------------
__global__ void k_scatter(const int* __restrict__ src, const int* __restrict__ dst) {
    int idx = blockIdx.x * blockDim.x + threadIdx.x;
    int stride = gridDim.x * blockDim.x;
    for (int e = idx; e < NE; e += stride) {
        int s = src[e], d = dst[e];
        int pd = atomicAdd(&g_cnt_dst[d], 1);
        if (pd < PAD) g_adj_dst[d * PAD + pd] = s;
        int ps = atomicAdd(&g_cnt_src[s], 1);
        if (ps < PAD) g_adj_src[s * PAD + ps] = d;
    }
}

__global__ void k_dis() {
    int v = blockIdx.x * blockDim.x + threadIdx.x;
    if (v < NN) {
        g_dis[v] = rsqrtf((float)g_cnt_dst[v] + 1.0f);
        g_doutdeg[v] = (float)g_cnt_src[v];
    }
}

// ---------------- weight prep: fp32 W[128][BN] -> bf16 hi/lo images [BN][128] -------
template <int BN>
__global__ void k_wprep(const float* __restrict__ W, int which) {
    int t = blockIdx.x * blockDim.x + threadIdx.x;   // one per (n, 8-k group)
    if (t >= BN * 16) return;
    __nv_bfloat16* outh = wimg(which, 0);
    __nv_bfloat16* outl = wimg(which, 1);
    int n = t >> 4;
    int kg = (t & 15) * 8;
    uint32_t h[4], l[4];
    #pragma unroll
    for (int i = 0; i < 4; i++) {
        float a = W[(size_t)(kg + 2 * i) * BN + n];
        float b = W[(size_t)(kg + 2 * i + 1) * BN + n];
        hilo2(a, b, h[i], l[i]);
    }
    *reinterpret_cast<uint4*>(outh + n * 128 + kg) = make_uint4(h[0], h[1], h[2], h[3]);
    *reinterpret_cast<uint4*>(outl + n * 128 + kg) = make_uint4(l[0], l[1], l[2], l[3]);
}

// ---------------- HMMA GEMM: C[M,BN] = A[M,128] @ W[128,BN] --------------------------
// 256 threads = 8 warps, CTA tile 128 x BN. bf16 hi/lo split (3 passes), fp32 acc.
// smem tiles padded to 136 bf16/row (bank-stride 4 -> conflict-free fragment loads).
// act: 0 none, 1 tanh, 2 relu
#define SROW 136
template <int BN>
__global__ void __launch_bounds__(256) k_gemm_mma(
    const float* Aext, int aSel,
    int whichW,
    const float* __restrict__ bias,
    int useDis,
    float* Cext, int cSel,
    int act)
{
    extern __shared__ __nv_bfloat16 dsm[];
    __nv_bfloat16* sAh = dsm;
    __nv_bfloat16* sAl = sAh + 128 * SROW;
    __nv_bfloat16* sBh = sAl + 128 * SROW;
    __nv_bfloat16* sBl = sBh + BN * SROW;

    const float* A = Aext ? Aext : buf_by_id(aSel);
    float* C = Cext ? Cext : buf_by_id(cSel);

    int tid = threadIdx.x;
    int wid = tid >> 5, lane = tid & 31;
    int rb = blockIdx.x * 128;

    // B tiles: cp.async bf16 hi/lo images ([BN][128] -> padded rows)
    {
        const __nv_bfloat16* Wh = wimg(whichW, 0);
        const __nv_bfloat16* Wl = wimg(whichW, 1);
        for (int i = tid; i < BN * 16; i += 256) {      // 16 x 16B chunks per row
            int n = i >> 4, c = (i & 15) * 8;           // c in bf16 units
            cp_async16(sBh + n * SROW + c, Wh + n * 128 + c);
            cp_async16(sBl + n * SROW + c, Wl + n * 128 + c);
        }
        cp_commit();
    }

    // A tile: fp32 load, hi/lo split, padded smem store
    {
        int row = tid >> 1;
        int ks0 = (tid & 1) << 6;   // 0 or 64
        const float* ap = A + (size_t)(rb + row) * 128 + ks0;
        __nv_bfloat16* dh = sAh + row * SROW + ks0;
        __nv_bfloat16* dl = sAl + row * SROW + ks0;
        #pragma unroll
        for (int j = 0; j < 8; j++) {
            float4 v0 = *reinterpret_cast<const float4*>(ap + j * 8);
            float4 v1 = *reinterpret_cast<const float4*>(ap + j * 8 + 4);
            uint32_t h[4], l[4];
            hilo2(v0.x, v0.y, h[0], l[0]);
            hilo2(v0.z, v0.w, h[1], l[1]);
            hilo2(v1.x, v1.y, h[2], l[2]);
            hilo2(v1.z, v1.w, h[3], l[3]);
            *reinterpret_cast<uint4*>(dh + j * 8) = make_uint4(h[0], h[1], h[2], h[3]);
            *reinterpret_cast<uint4*>(dl + j * 8) = make_uint4(l[0], l[1], l[2], l[3]);
        }
    }

    cp_wait<0>();
    __syncthreads();

    // compute: warp wid owns rows [wid*16, wid*16+16), all BN cols
    const int NT = BN / 8;
    float acc[NT][4];
    #pragma unroll
    for (int nt = 0; nt < NT; nt++)
        #pragma unroll
        for (int j = 0; j < 4; j++) acc[nt][j] = 0.f;

    int mrow = lane >> 2;          // 0..7
    int kq = (lane & 3) * 2;       // 0,2,4,6
    const __nv_bfloat16* a_r0 = dsm /*sAh*/ + (wid * 16 + mrow) * SROW + kq;

    #pragma unroll
    for (int split = 0; split < 3; split++) {
        const __nv_bfloat16* sa = (split == 2) ? sAl : sAh;
        const __nv_bfloat16* sb = (split == 1) ? sBl : sBh;
        const __nv_bfloat16* ar = sa + (wid * 16 + mrow) * SROW + kq;
        const __nv_bfloat16* br = sb + mrow * SROW + kq;
        #pragma unroll
        for (int k = 0; k < 8; k++) {
            int kb = k * 16;
            uint32_t a0 = *reinterpret_cast<const uint32_t*>(ar + kb);
            uint32_t a1 = *reinterpret_cast<const uint32_t*>(ar + 8 * SROW + kb);
            uint32_t a2 = *reinterpret_cast<const uint32_t*>(ar + kb + 8);
            uint32_t a3 = *reinterpret_cast<const uint32_t*>(ar + 8 * SROW + kb + 8);
            #pragma unroll
            for (int nt = 0; nt < NT; nt++) {
                uint32_t b0 = *reinterpret_cast<const uint32_t*>(br + nt * 8 * SROW + kb);
                uint32_t b1 = *reinterpret_cast<const uint32_t*>(br + nt * 8 * SROW + kb + 8);
                mma16816(acc[nt], a0, a1, a2, a3, b0, b1);
            }
        }
    }
    (void)a_r0;

    // epilogue: d0,d1 -> (r0, col..col+1); d2,d3 -> (r0+8, col..col+1)
    {
        int r0 = rb + wid * 16 + (lane >> 2);
        int r1 = r0 + 8;
        float rs0 = useDis ? g_dis[r0] : 1.0f;
        float rs1 = useDis ? g_dis[r1] : 1.0f;
        float* c0 = C + (size_t)r0 * BN;
        float* c1 = C + (size_t)r1 * BN;
        #pragma unroll
        for (int nt = 0; nt < NT; nt++) {
            int col = nt * 8 + (lane & 3) * 2;
            float bv0 = bias ? bias[col] : 0.f;
            float bv1 = bias ? bias[col + 1] : 0.f;
            float v00 = (acc[nt][0] + bv0) * rs0;
            float v01 = (acc[nt][1] + bv1) * rs0;
            float v10 = (acc[nt][2] + bv0) * rs1;
            float v11 = (acc[nt][3] + bv1) * rs1;
            if (act == 1) {
                v00 = tanhf(v00); v01 = tanhf(v01);
                v10 = tanhf(v10); v11 = tanhf(v11);
            } else if (act == 2) {
                v00 = fmaxf(v00, 0.f); v01 = fmaxf(v01, 0.f);
                v10 = fmaxf(v10, 0.f); v11 = fmaxf(v11, 0.f);
            }
            *reinterpret_cast<float2*>(c0 + col) = make_float2(v00, v01);
            *reinterpret_cast<float2*>(c1 + col) = make_float2(v10, v11);
        }
    }
}

// ---------------- small scalar GEMM (pooled projection, 512 rows) -------------------
template <int BN>
__global__ void __launch_bounds__(256) k_gemm(
    const float* Aext, int aSel,
    const float* __restrict__ W,
    const float* __restrict__ bias,
    int useDis,
    float* Cext, int cSel,
    int act)
{
    const int TN = BN / 16;
    const float* A = Aext ? Aext : buf_by_id(aSel);
    float* C = Cext ? Cext : buf_by_id(cSel);

    __shared__ float sA[32][68];
    __shared__ float sW[32][BN];

    int tid = threadIdx.x;
    int ty = tid >> 4, tx = tid & 15;
    int rb = blockIdx.x * 64;

    float acc[4][TN];
    #pragma unroll
    for (int i = 0; i < 4; i++)
        #pragma unroll
        for (int j = 0; j < TN; j++) acc[i][j] = 0.f;

    for (int k0 = 0; k0 < 128; k0 += 32) {
        #pragma unroll
        for (int i = 0; i < 2; i++) {
            int idx = tid + i * 256;
            int r = idx >> 3, c4 = (idx & 7) << 2;
            float4 v = *reinterpret_cast<const float4*>(A + (size_t)(rb + r) * 128 + k0 + c4);
            sA[c4 + 0][r] = v.x; sA[c4 + 1][r] = v.y;
            sA[c4 + 2][r] = v.z; sA[c4 + 3][r] = v.w;
        }
        #pragma unroll
        for (int i = 0; i < BN / 32; i++) {
            int idx = tid + i * 256;
            int r = idx / (BN / 4), c4 = (idx % (BN / 4)) << 2;
            *reinterpret_cast<float4*>(&sW[r][c4]) =
                *reinterpret_cast<const float4*>(W + (size_t)(k0 + r) * BN + c4);
        }
        __syncthreads();
        #pragma unroll
        for (int kk = 0; kk < 32; kk++) {
            float4 av = *reinterpret_cast<const float4*>(&sA[kk][ty * 4]);
            float a[4] = {av.x, av.y, av.z, av.w};
            float b[TN];
            #pragma unroll
            for (int jg = 0; jg < TN / 4; jg++) {
                float4 bv = *reinterpret_cast<const float4*>(&sW[kk][tx * TN + jg * 4]);
                b[jg * 4 + 0] = bv.x; b[jg * 4 + 1] = bv.y;
                b[jg * 4 + 2] = bv.z; b[jg * 4 + 3] = bv.w;
            }
            #pragma unroll
            for (int i = 0; i < 4; i++)
                #pragma unroll
                for (int j = 0; j < TN; j++)
                    acc[i][j] = fmaf(a[i], b[j], acc[i][j]);
        }
        __syncthreads();
    }

    #pragma unroll
    for (int i = 0; i < 4; i++) {
        int row = rb + ty * 4 + i;
        float rs = useDis ? g_dis[row] : 1.0f;
        #pragma unroll
        for (int j = 0; j < TN; j++) {
            int col = tx * TN + j;
            float v = acc[i][j];
            if (bias) v += bias[col];
            v *= rs;
            if (act == 1) v = tanhf(v);
            else if (act == 2) v = fmaxf(v, 0.f);
            C[(size_t)row * BN + col] = v;
        }
    }
}

// ---------------- GCN aggregation (F=128): warp per node, MLP-4 gather --------------
__global__ void __launch_bounds__(256) k_agg_f128(const float* __restrict__ bias, int relu) {
    int w = (blockIdx.x * blockDim.x + threadIdx.x) >> 5;
    int lane = threadIdx.x & 31;
    if (w >= NN) return;
    const float* hh = g_bufA;
    float4 acc0 = *reinterpret_cast<const float4*>(hh + (size_t)w * 128 + lane * 4);
    float4 acc1 = make_float4(0.f, 0.f, 0.f, 0.f);
    float4 acc2 = make_float4(0.f, 0.f, 0.f, 0.f);
    float4 acc3 = make_float4(0.f, 0.f, 0.f, 0.f);
    int n = g_cnt_dst[w];
    const int* lst = g_adj_dst + (size_t)w * PAD;
    int e = 0;
    for (; e + 4 <= n; e += 4) {
        int u0 = __ldg(&lst[e]),     u1 = __ldg(&lst[e + 1]);
        int u2 = __ldg(&lst[e + 2]), u3 = __ldg(&lst[e + 3]);
        float4 v0 = *reinterpret_cast<const float4*>(hh + (size_t)u0 * 128 + lane * 4);
        float4 v1 = *reinterpret_cast<const float4*>(hh + (size_t)u1 * 128 + lane * 4);
        float4 v2 = *reinterpret_cast<const float4*>(hh + (size_t)u2 * 128 + lane * 4);
        float4 v3 = *reinterpret_cast<const float4*>(hh + (size_t)u3 * 128 + lane * 4);
        acc0.x += v0.x; acc0.y += v0.y; acc0.z += v0.z; acc0.w += v0.w;
        acc1.x += v1.x; acc1.y += v1.y; acc1.z += v1.z; acc1.w += v1.w;
        acc2.x += v2.x; acc2.y += v2.y; acc2.z += v2.z; acc2.w += v2.w;
        acc3.x += v3.x; acc3.y += v3.y; acc3.z += v3.z; acc3.w += v3.w;
    }
    for (; e < n; e++) {
        int u = __ldg(&lst[e]);
        float4 v = *reinterpret_cast<const float4*>(hh + (size_t)u * 128 + lane * 4);
        acc0.x += v.x; acc0.y += v.y; acc0.z += v.z; acc0.w += v.w;
    }
    acc0.x += acc1.x + acc2.x + acc3.x;
    acc0.y += acc1.y + acc2.y + acc3.y;
    acc0.z += acc1.z + acc2.z + acc3.z;
    acc0.w += acc1.w + acc2.w + acc3.w;
    float d = g_dis[w];
    float4 bb = *reinterpret_cast<const float4*>(bias + lane * 4);
    float4 r;
    r.x = acc0.x * d + bb.x; r.y = acc0.y * d + bb.y;
    r.z = acc0.z * d + bb.z; r.w = acc0.w * d + bb.w;
    if (relu) {
        r.x = fmaxf(r.x, 0.f); r.y = fmaxf(r.y, 0.f);
        r.z = fmaxf(r.z, 0.f); r.w = fmaxf(r.w, 0.f);
    }
    *reinterpret_cast<float4*>(g_bufB + (size_t)w * 128 + lane * 4) = r;
}

// ---------------- warp reductions ----------------
__device__ __forceinline__ float wredmax(float v) {
    #pragma unroll
    for (int o = 16; o; o >>= 1) v = fmaxf(v, __shfl_xor_sync(FULLM, v, o));
    return v;
}
__device__ __forceinline__ float wredsum(float v) {
    #pragma unroll
    for (int o = 16; o; o >>= 1) v += __shfl_xor_sync(FULLM, v, o);
    return v;
}

// ---------------- double softmax + mincut_den partial ----------------
__global__ void __launch_bounds__(256) k_softmax() {
    int n = (blockIdx.x * blockDim.x + threadIdx.x) >> 5;
    int lane = threadIdx.x & 31;
    if (n >= NN) return;
    float2 z = *reinterpret_cast<const float2*>(g_s_buf + (size_t)n * 64 + lane * 2);
    float m = wredmax(fmaxf(z.x, z.y));
    float ex = expf(z.x - m), ey = expf(z.y - m);
    float s = wredsum(ex + ey);
    float px = ex / s, py = ey / s;
    float m2 = wredmax(fmaxf(px, py));
    float ex2 = expf(px - m2), ey2 = expf(py - m2);
    float s2 = wredsum(ex2 + ey2);
    float qx = ex2 / s2, qy = ey2 / s2;
    *reinterpret_cast<float2*>(g_s_buf + (size_t)n * 64 + lane * 2) = make_float2(qx, qy);
    float t = wredsum(qx * qx + qy * qy);
    if (lane == 0) atomicAdd(&g_den[n >> 12], g_doutdeg[n] * t);
}

// ---------------- As[u] = sum_{u->v} s_d[v] ----------------
__global__ void __launch_bounds__(256) k_agg_as() {
    int w = (blockIdx.x * blockDim.x + threadIdx.x) >> 5;
    int lane = threadIdx.x & 31;
    if (w >= NN) return;
    float2 a0 = make_float2(0.f, 0.f), a1 = make_float2(0.f, 0.f);
    float2 a2 = make_float2(0.f, 0.f), a3 = make_float2(0.f, 0.f);
    int n = g_cnt_src[w];
    const int* lst = g_adj_src + (size_t)w * PAD;
    int e = 0;
    for (; e + 4 <= n; e += 4) {
        int v0 = __ldg(&lst[e]),     v1 = __ldg(&lst[e + 1]);
        int v2 = __ldg(&lst[e + 2]), v3 = __ldg(&lst[e + 3]);
        float2 t0 = *reinterpret_cast<const float2*>(g_s_buf + (size_t)v0 * 64 + lane * 2);
        float2 t1 = *reinterpret_cast<const float2*>(g_s_buf + (size_t)v1 * 64 + lane * 2);
        float2 t2 = *reinterpret_cast<const float2*>(g_s_buf + (size_t)v2 * 64 + lane * 2);
        float2 t3 = *reinterpret_cast<const float2*>(g_s_buf + (size_t)v3 * 64 + lane * 2);
        a0.x += t0.x; a0.y += t0.y;
        a1.x += t1.x; a1.y += t1.y;
        a2.x += t2.x; a2.y += t2.y;
        a3.x += t3.x; a3.y += t3.y;
    }
    for (; e < n; e++) {
        int v = __ldg(&lst[e]);
        float2 t = *reinterpret_cast<const float2*>(g_s_buf + (size_t)v * 64 + lane * 2);
        a0.x += t.x; a0.y += t.y;
    }
    a0.x += a1.x + a2.x + a3.x;
    a0.y += a1.y + a2.y + a3.y;
    *reinterpret_cast<float2*>(g_As + (size_t)w * 64 + lane * 2) = a0;
}

// ---------------- fused pooling reductions ----------------
__global__ void __launch_bounds__(256) k_pool() {
    int b = blockIdx.x >> 5;
    int chunk = blockIdx.x & 31;
    int tid = threadIdx.x;
    int ty = tid >> 4, tx = tid & 15;

    __shared__ float s_t[16][64];
    __shared__ float a_t[16][64];
    __shared__ float h_t[16][128];

    float racc[4][4] = {}, sacc[4][4] = {}, oacc[4][8] = {};

    for (int t = 0; t < 8; t++) {
        int nbase = b * NPG + chunk * 128 + t * 16;
        {
            int r = tid >> 4, c4 = (tid & 15) << 2;
            *reinterpret_cast<float4*>(&s_t[r][c4]) =
                *reinterpret_cast<const float4*>(g_s_buf + (size_t)(nbase + r) * 64 + c4);
            *reinterpret_cast<float4*>(&a_t[r][c4]) =
                *reinterpret_cast<const float4*>(g_As + (size_t)(nbase + r) * 64 + c4);
        }
        #pragma unroll
        for (int i = 0; i < 2; i++) {
            int idx = tid + i * 256;
            int r = idx >> 5, c4 = (idx & 31) << 2;
            *reinterpret_cast<float4*>(&h_t[r][c4]) =
                *reinterpret_cast<const float4*>(g_bufB + (size_t)(nbase + r) * 128 + c4);
        }
        __syncthreads();
        #pragma unroll
        for (int n = 0; n < 16; n++) {
            float4 skv = *reinterpret_cast<const float4*>(&s_t[n][ty * 4]);
            float4 ajv = *reinterpret_cast<const float4*>(&a_t[n][tx * 4]);
            float4 sjv = *reinterpret_cast<const float4*>(&s_t[n][tx * 4]);
            float4 h0v = *reinterpret_cast<const float4*>(&h_t[n][tx * 8]);
            float4 h1v = *reinterpret_cast<const float4*>(&h_t[n][tx * 8 + 4]);
            float sk[4] = {skv.x, skv.y, skv.z, skv.w};
            float aj[4] = {ajv.x, ajv.y, ajv.z, ajv.w};
            float sj[4] = {sjv.x, sjv.y, sjv.z, sjv.w};
            float hf[8] = {h0v.x, h0v.y, h0v.z, h0v.w, h1v.x, h1v.y, h1v.z, h1v.w};
            #pragma unroll
            for (int i = 0; i < 4; i++) {
                #pragma unroll
                for (int j = 0; j < 4; j++) {
                    racc[i][j] = fmaf(sk[i], aj[j], racc[i][j]);
                    sacc[i][j] = fmaf(sk[i], sj[j], sacc[i][j]);
                }
                #pragma unroll
                for (int j = 0; j < 8; j++)
                    oacc[i][j] = fmaf(sk[i], hf[j], oacc[i][j]);
            }
        }
        __syncthreads();
    }

    #pragma unroll
    for (int i = 0; i < 4; i++) {
        int k = ty * 4 + i;
        #pragma unroll
        for (int j = 0; j < 4; j++) {
            int c = tx * 4 + j;
            atomicAdd(&g_outadj[b * 4096 + k * 64 + c], racc[i][j]);
            atomicAdd(&g_ssm[b * 4096 + k * 64 + c], sacc[i][j]);
        }
        #pragma unroll
        for (int j = 0; j < 8; j++) {
            int f = tx * 8 + j;
            atomicAdd(&g_out_pool[(size_t)(b * 64 + k) * 128 + f], oacc[i][j]);
        }
    }
}

// ---------------- per-graph finalize ----------------
__device__ __forceinline__ float block_reduce256(float v, float* red) {
    int tid = threadIdx.x;
    red[tid] = v;
    __syncthreads();
    for (int s = 128; s > 0; s >>= 1) {
        if (tid < s) red[tid] += red[tid + s];
        __syncthreads();
    }
    float r = red[0];
    __syncthreads();
    return r;
}

__global__ void __launch_bounds__(256) k_finalize(float* __restrict__ out) {
    int b = blockIdx.x;
    int tid = threadIdx.x;
    __shared__ float oa[4096];
    __shared__ float red[256];
    __shared__ float dsh[64];

    for (int i = tid; i < 4096; i += 256) oa[i] = g_outadj[b * 4096 + i];
    __syncthreads();

    float tv = (tid < 64) ? oa[tid * 65] : 0.f;
    float trace = block_reduce256(tv, red);

    float s2 = 0.f;
    for (int i = tid; i < 4096; i += 256) {
        float v = g_ssm[b * 4096 + i];
        s2 += v * v;
    }
    float ssn = sqrtf(block_reduce256(s2, red));

    float o2 = 0.f;
    for (int i = tid; i < 4096; i += 256) {
        float v = g_ssm[b * 4096 + i] / ssn;
        if (i % 65 == 0) v -= 0.125f;
        o2 += v * v;
    }
    float ortho = sqrtf(block_reduce256(o2, red));

    if (tid < 64) {
        float rs = 0.f;
        for (int j = 0; j < 64; j++)
            if (j != tid) rs += oa[tid * 64 + j];
        dsh[tid] = sqrtf(rs) + 1e-15f;
    }
    __syncthreads();

    for (int i = tid; i < 4096; i += 256) {
        int k = i >> 6, j = i & 63;
        float v = (k == j) ? 0.f : oa[i] / (dsh[k] * dsh[j]);
        out[OA_OFF + b * 4096 + i] = v;
    }

    if (tid == 0) {
        g_mb[b] = -trace / g_den[b];
        g_ob[b] = ortho;
    }
}

__global__ void k_scalars(float* __restrict__ out) {
    int tid = threadIdx.x;
    out[PB_OFF + tid] = (float)(tid >> 6);
    if (tid == 0) {
        float m = 0.f, o = 0.f;
        for (int b = 0; b < NG; b++) { m += g_mb[b]; o += g_ob[b]; }
        out[ML_OFF] = m / (float)NG;
        out[OL_OFF] = o / (float)NG;
    }
}

// ---------------- launcher ----------------
extern "C" void kernel_launch(void* const* d_in, const int* in_sizes, int n_in,
                              void* d_out, int out_size) {
    (void)in_sizes; (void)n_in; (void)out_size;
    const float* x   = (const float*)d_in[0];
    const int*   ei  = (const int*)d_in[1];
    const float* W1  = (const float*)d_in[3];
    const float* b1  = (const float*)d_in[4];
    const float* W2  = (const float*)d_in[5];
    const float* b2  = (const float*)d_in[6];
    const float* Wa1 = (const float*)d_in[7];
    const float* ba1 = (const float*)d_in[8];
    const float* Wa2 = (const float*)d_in[9];
    const float* ba2 = (const float*)d_in[10];
    const float* Wo  = (const float*)d_in[11];
    const float* bo  = (const float*)d_in[12];
    float* out = (float*)d_out;
    const int* src = ei;
    const int* dst = ei + NE;

    // dynamic smem: (128 A-rows hi+lo + BN B-rows hi+lo) * 136 bf16
    const int SM128 = (128 * 2 + 128 * 2) * SROW * 2;   // 139264 B
    const int SM64  = (128 * 2 + 64 * 2) * SROW * 2;    // 104448 B
    cudaFuncSetAttribute(k_gemm_mma<128>, cudaFuncAttributeMaxDynamicSharedMemorySize, SM128);
    cudaFuncSetAttribute(k_gemm_mma<64>,  cudaFuncAttributeMaxDynamicSharedMemorySize, SM64);

    // weight prep (bf16 hi/lo [n][k] images)
    k_wprep<128><<<8, 256>>>(W1, 0);
    k_wprep<128><<<8, 256>>>(W2, 1);
    k_wprep<128><<<8, 256>>>(Wa1, 2);
    k_wprep<64><<<4, 256>>>(Wa2, 3);

    k_zero<<<256, 256>>>();
    k_scatter<<<512, 256>>>(src, dst);
    k_dis<<<128, 256>>>();

    // GCN layer 1: hh = (x @ W1) * dis -> bufA ; h1 = relu((agg+self)*dis + b1) -> bufB
    k_gemm_mma<128><<<NN / 128, 256, SM128>>>(x, -1, 0, nullptr, 1, nullptr, 0, 0);
    k_agg_f128<<<NN / 8, 256>>>(b1, 1);

    // GCN layer 2
    k_gemm_mma<128><<<NN / 128, 256, SM128>>>(nullptr, 1, 1, nullptr, 1, nullptr, 0, 0);
    k_agg_f128<<<NN / 8, 256>>>(b2, 0);

    // assignment MLP: a = tanh(h2 @ Wa1 + ba1) -> bufA ; logits -> g_s_buf
    k_gemm_mma<128><<<NN / 128, 256, SM128>>>(nullptr, 1, 2, ba1, 0, nullptr, 0, 1);
    k_gemm_mma<64><<<NN / 128, 256, SM64>>>(nullptr, 0, 3, ba2, 0, nullptr, 2, 0);

    // double softmax (+ mincut_den), As = A @ s_d
    k_softmax<<<NN / 8, 256>>>();
    k_agg_as<<<NN / 8, 256>>>();

    // fused pooled reductions
    k_pool<<<NG * 32, 256>>>();

    // pooled_x = relu(out_pool @ Wo + bo)
    k_gemm<128><<<(NG * KD) / 64, 256>>>(nullptr, 3, Wo, bo, 0, out, -1, 2);

    k_finalize<<<NG, 256>>>(out);
    k_scalars<<<1, 512>>>(out);
}

// round 13
// speedup vs baseline: 1.1622x; 1.1014x over previous
#include <cuda_runtime.h>
#include <cuda_bf16.h>
#include <stdint.h>

// ---------------- problem constants ----------------
#define NN   32768
#define NG   8
#define NPG  4096
#define NE   524288
#define FD   128
#define KD   64
#define PAD  128

#define PX_OFF 0
#define OA_OFF 65536
#define PB_OFF 98304
#define ML_OFF 98816
#define OL_OFF 98817

#define FULLM 0xffffffffu

// ---------------- device scratch ----------------
static __device__ __align__(16) float g_bufA[NN * FD];
static __device__ __align__(16) float g_bufB[NN * FD];
static __device__ __align__(16) float g_s_buf[NN * KD];
static __device__ __align__(16) float g_As[NN * KD];
static __device__ __align__(16) float g_out_pool[NG * KD * FD];
static __device__ float g_outadj[NG * KD * KD];
static __device__ float g_ssm[NG * KD * KD];
static __device__ float g_den[NG];
static __device__ float g_mb[NG];
static __device__ float g_ob[NG];
static __device__ float g_dis[NN];
static __device__ float g_doutdeg[NN];
static __device__ int   g_cnt_dst[NN];
static __device__ int   g_cnt_src[NN];
static __device__ int   g_adj_dst[NN * PAD];
static __device__ int   g_adj_src[NN * PAD];
// bf16 hi/lo weight images, [n][k] row-major (n rows of 128 k)
static __device__ __align__(16) __nv_bfloat16 g_wh1[16384], g_wl1[16384];
static __device__ __align__(16) __nv_bfloat16 g_wh2[16384], g_wl2[16384];
static __device__ __align__(16) __nv_bfloat16 g_wha1[16384], g_wla1[16384];
static __device__ __align__(16) __nv_bfloat16 g_wha2[8192],  g_wla2[8192];
static __device__ __align__(16) __nv_bfloat16 g_who[16384],  g_wlo[16384];

__device__ __forceinline__ float* buf_by_id(int id) {
    switch (id) {
        case 0: return g_bufA;
        case 1: return g_bufB;
        case 2: return g_s_buf;
        default: return g_out_pool;
    }
}
__device__ __forceinline__ __nv_bfloat16* wimg(int which, int lo) {
    switch (which) {
        case 0: return lo ? g_wl1 : g_wh1;
        case 1: return lo ? g_wl2 : g_wh2;
        case 2: return lo ? g_wla1 : g_wha1;
        case 3: return lo ? g_wla2 : g_wha2;
        default: return lo ? g_wlo : g_who;
    }
}

// ---------------- async / mma helpers ----------------
__device__ __forceinline__ void cp_async16(void* smem_dst, const void* gmem_src) {
    unsigned saddr = (unsigned)__cvta_generic_to_shared(smem_dst);
    asm volatile("cp.async.cg.shared.global [%0], [%1], 16;\n" :: "r"(saddr), "l"(gmem_src));
}
__device__ __forceinline__ void cp_commit() { asm volatile("cp.async.commit_group;\n"); }
template <int N>
__device__ __forceinline__ void cp_wait() { asm volatile("cp.async.wait_group %0;\n" :: "n"(N)); }

__device__ __forceinline__ void hilo2(float a, float b, uint32_t& h, uint32_t& l) {
    __nv_bfloat162 hh = __floats2bfloat162_rn(a, b);
    __nv_bfloat162 ll = __floats2bfloat162_rn(a - __bfloat162float(hh.x),
                                              b - __bfloat162float(hh.y));
    h = *reinterpret_cast<uint32_t*>(&hh);
    l = *reinterpret_cast<uint32_t*>(&ll);
}

__device__ __forceinline__ void mma16816(float* d,
                                         uint32_t a0, uint32_t a1, uint32_t a2, uint32_t a3,
                                         uint32_t b0, uint32_t b1) {
    asm volatile(
        "mma.sync.aligned.m16n8k16.row.col.f32.bf16.bf16.f32 "
        "{%0,%1,%2,%3}, {%4,%5,%6,%7}, {%8,%9}, {%0,%1,%2,%3};"
        : "+f"(d[0]), "+f"(d[1]), "+f"(d[2]), "+f"(d[3])
        : "r"(a0), "r"(a1), "r"(a2), "r"(a3), "r"(b0), "r"(b1));
}
__device__ __forceinline__ void ldsm4(uint32_t* r, uint32_t addr) {
    asm volatile("ldmatrix.sync.aligned.m8n8.x4.shared.b16 {%0,%1,%2,%3}, [%4];"
                 : "=r"(r[0]), "=r"(r[1]), "=r"(r[2]), "=r"(r[3]) : "r"(addr));
}

// ---------------- fused prep: zero scratch + all weight hi/lo images ----------------
__device__ __forceinline__ void wprep_one(const float* __restrict__ W,
                                          __nv_bfloat16* oh, __nv_bfloat16* ol,
                                          int BN, int t) {
    int n = t >> 4;
    int kg = (t & 15) * 8;
    uint32_t h[4], l[4];
    #pragma unroll
    for (int i = 0; i < 4; i++) {
        float a = W[(size_t)(kg + 2 * i) * BN + n];
        float b = W[(size_t)(kg + 2 * i + 1) * BN + n];
        hilo2(a, b, h[i], l[i]);
    }
    *reinterpret_cast<uint4*>(oh + n * 128 + kg) = make_uint4(h[0], h[1], h[2], h[3]);
    *reinterpret_cast<uint4*>(ol + n * 128 + kg) = make_uint4(l[0], l[1], l[2], l[3]);
}

__global__ void k_prep(const float* __restrict__ W1, const float* __restrict__ W2,
                       const float* __restrict__ Wa1, const float* __restrict__ Wa2,
                       const float* __restrict__ Wo) {
    int i = blockIdx.x * blockDim.x + threadIdx.x;   // 65536 threads
    if (i < NN) {
        g_cnt_dst[i] = 0; g_cnt_src[i] = 0;
        g_outadj[i] = 0.f; g_ssm[i] = 0.f;
    }
    g_out_pool[i] = 0.f;
    if (i < NG) g_den[i] = 0.f;

    if (i < 2048)       wprep_one(W1,  g_wh1,  g_wl1,  128, i);
    else if (i < 4096)  wprep_one(W2,  g_wh2,  g_wl2,  128, i - 2048);
    else if (i < 6144)  wprep_one(Wa1, g_wha1, g_wla1, 128, i - 4096);
    else if (i < 7168)  wprep_one(Wa2, g_wha2, g_wla2, 64,  i - 6144);
    else if (i < 9216)  wprep_one(Wo,  g_who,  g_wlo,  128, i - 7168);
}

// ---------------- adjacency build ----------------
__global__ void k_scatter(const int* __restrict__ src, const int* __restrict__ dst) {
    int idx = blockIdx.x * blockDim.x + threadIdx.x;
    int stride = gridDim.x * blockDim.x;
    for (int e = idx; e < NE; e += stride) {
        int s = src[e], d = dst[e];
        int pd = atomicAdd(&g_cnt_dst[d], 1);
        if (pd < PAD) g_adj_dst[d * PAD + pd] = s;
        int ps = atomicAdd(&g_cnt_src[s], 1);
        if (ps < PAD) g_adj_src[s * PAD + ps] = d;
    }
}

__global__ void k_dis() {
    int v = blockIdx.x * blockDim.x + threadIdx.x;
    if (v < NN) {
        g_dis[v] = rsqrtf((float)g_cnt_dst[v] + 1.0f);
        g_doutdeg[v] = (float)g_cnt_src[v];
    }
}

// ---------------- HMMA GEMM: C[M,BN] = A[M,128] @ W[128,BN] --------------------------
// 256 threads = 8 warps as 2m x 4n; warp tile 64 x (BN/4). bf16 hi/lo (3 passes).
// ldmatrix.x4 fragment loads from pad-136 smem rows (272B stride -> conflict-free).
#define SROW 136
template <int BN>
__global__ void __launch_bounds__(256) k_gemm_mma(
    const float* Aext, int aSel,
    int whichW,
    const float* __restrict__ bias,
    int useDis,
    float* Cext, int cSel,
    int act)   // 0 none, 1 tanh, 2 relu
{
    extern __shared__ __nv_bfloat16 dsm[];
    __nv_bfloat16* sAh = dsm;
    __nv_bfloat16* sAl = sAh + 128 * SROW;
    __nv_bfloat16* sBh = sAl + 128 * SROW;
    __nv_bfloat16* sBl = sBh + BN * SROW;

    const float* A = Aext ? Aext : buf_by_id(aSel);
    float* C = Cext ? Cext : buf_by_id(cSel);

    int tid = threadIdx.x;
    int wid = tid >> 5, lane = tid & 31;
    int rb = blockIdx.x * 128;

    // B tiles: cp.async bf16 hi/lo images ([BN][128] -> padded rows)
    {
        const __nv_bfloat16* Wh = wimg(whichW, 0);
        const __nv_bfloat16* Wl = wimg(whichW, 1);
        for (int i = tid; i < BN * 16; i += 256) {
            int n = i >> 4, c = (i & 15) * 8;
            cp_async16(sBh + n * SROW + c, Wh + n * 128 + c);
            cp_async16(sBl + n * SROW + c, Wl + n * 128 + c);
        }
        cp_commit();
    }

    // A tile: fp32 load, hi/lo split, padded smem store
    {
        int row = tid >> 1;
        int ks0 = (tid & 1) << 6;
        const float* ap = A + (size_t)(rb + row) * 128 + ks0;
        __nv_bfloat16* dh = sAh + row * SROW + ks0;
        __nv_bfloat16* dl = sAl + row * SROW + ks0;
        #pragma unroll
        for (int j = 0; j < 8; j++) {
            float4 v0 = *reinterpret_cast<const float4*>(ap + j * 8);
            float4 v1 = *reinterpret_cast<const float4*>(ap + j * 8 + 4);
            uint32_t h[4], l[4];
            hilo2(v0.x, v0.y, h[0], l[0]);
            hilo2(v0.z, v0.w, h[1], l[1]);
            hilo2(v1.x, v1.y, h[2], l[2]);
            hilo2(v1.z, v1.w, h[3], l[3]);
            *reinterpret_cast<uint4*>(dh + j * 8) = make_uint4(h[0], h[1], h[2], h[3]);
            *reinterpret_cast<uint4*>(dl + j * 8) = make_uint4(l[0], l[1], l[2], l[3]);
        }
    }

    cp_wait<0>();
    __syncthreads();

    const int NF = BN / 32;             // n-frags per warp (4 for BN=128, 2 for BN=64)
    const int NG2 = NF / 2;             // ldmatrix groups for B
    int wm = wid & 1, wn = wid >> 1;
    int r8 = lane & 7, tl = lane >> 3;

    uint32_t uAh = (uint32_t)__cvta_generic_to_shared(sAh);
    uint32_t uAl = (uint32_t)__cvta_generic_to_shared(sAl);
    uint32_t uBh = (uint32_t)__cvta_generic_to_shared(sBh);
    uint32_t uBl = (uint32_t)__cvta_generic_to_shared(sBl);

    // per-lane ldmatrix byte offsets (A: tiles {r0k0, r8k0, r0k8, r8k8})
    uint32_t aoff[4];
    #pragma unroll
    for (int f = 0; f < 4; f++)
        aoff[f] = ((uint32_t)((wm * 64 + f * 16 + (tl & 1) * 8 + r8) * SROW + (tl >> 1) * 8)) * 2;
    // B: tiles {nLow k0, nLow k8, nHigh k0, nHigh k8}
    uint32_t boff[NG2];
    #pragma unroll
    for (int j = 0; j < NG2; j++)
        boff[j] = ((uint32_t)((wn * (BN / 4) + j * 16 + (tl >> 1) * 8 + r8) * SROW + (tl & 1) * 8)) * 2;

    float acc[4][NF][4];
    #pragma unroll
    for (int f = 0; f < 4; f++)
        #pragma unroll
        for (int g = 0; g < NF; g++)
            #pragma unroll
            for (int j = 0; j < 4; j++) acc[f][g][j] = 0.f;

    #pragma unroll
    for (int split = 0; split < 3; split++) {
        uint32_t ua = (split == 2) ? uAl : uAh;
        uint32_t ub = (split == 1) ? uBl : uBh;
        #pragma unroll
        for (int k = 0; k < 8; k++) {
            uint32_t kb2 = (uint32_t)k * 32;   // 16 bf16 = 32 bytes
            uint32_t a[4][4];
            #pragma unroll
            for (int f = 0; f < 4; f++) ldsm4(a[f], ua + aoff[f] + kb2);
            uint32_t b[NF][2];
            #pragma unroll
            for (int j = 0; j < NG2; j++) {
                uint32_t t4[4];
                ldsm4(t4, ub + boff[j] + kb2);
                b[2 * j][0] = t4[0];     b[2 * j][1] = t4[1];
                b[2 * j + 1][0] = t4[2]; b[2 * j + 1][1] = t4[3];
            }
            #pragma unroll
            for (int f = 0; f < 4; f++)
                #pragma unroll
                for (int g = 0; g < NF; g++)
                    mma16816(acc[f][g], a[f][0], a[f][1], a[f][2], a[f][3], b[g][0], b[g][1]);
        }
    }

    // epilogue
    #pragma unroll
    for (int f = 0; f < 4; f++) {
        int r0 = rb + wm * 64 + f * 16 + (lane >> 2);
        int r1 = r0 + 8;
        float rs0 = useDis ? g_dis[r0] : 1.0f;
        float rs1 = useDis ? g_dis[r1] : 1.0f;
        float* c0 = C + (size_t)r0 * BN;
        float* c1 = C + (size_t)r1 * BN;
        #pragma unroll
        for (int g = 0; g < NF; g++) {
            int col = wn * (BN / 4) + g * 8 + (lane & 3) * 2;
            float bv0 = bias ? bias[col] : 0.f;
            float bv1 = bias ? bias[col + 1] : 0.f;
            float v00 = (acc[f][g][0] + bv0) * rs0;
            float v01 = (acc[f][g][1] + bv1) * rs0;
            float v10 = (acc[f][g][2] + bv0) * rs1;
            float v11 = (acc[f][g][3] + bv1) * rs1;
            if (act == 1) {
                v00 = tanhf(v00); v01 = tanhf(v01);
                v10 = tanhf(v10); v11 = tanhf(v11);
            } else if (act == 2) {
                v00 = fmaxf(v00, 0.f); v01 = fmaxf(v01, 0.f);
                v10 = fmaxf(v10, 0.f); v11 = fmaxf(v11, 0.f);
            }
            *reinterpret_cast<float2*>(c0 + col) = make_float2(v00, v01);
            *reinterpret_cast<float2*>(c1 + col) = make_float2(v10, v11);
        }
    }
}

// ---------------- GCN aggregation (F=128): warp per node, MLP-4 gather --------------
__global__ void __launch_bounds__(256) k_agg_f128(const float* __restrict__ bias, int relu) {
    int w = (blockIdx.x * blockDim.x + threadIdx.x) >> 5;
    int lane = threadIdx.x & 31;
    if (w >= NN) return;
    const float* hh = g_bufA;
    float4 acc0 = *reinterpret_cast<const float4*>(hh + (size_t)w * 128 + lane * 4);
    float4 acc1 = make_float4(0.f, 0.f, 0.f, 0.f);
    float4 acc2 = make_float4(0.f, 0.f, 0.f, 0.f);
    float4 acc3 = make_float4(0.f, 0.f, 0.f, 0.f);
    int n = g_cnt_dst[w];
    const int* lst = g_adj_dst + (size_t)w * PAD;
    int e = 0;
    for (; e + 4 <= n; e += 4) {
        int u0 = __ldg(&lst[e]),     u1 = __ldg(&lst[e + 1]);
        int u2 = __ldg(&lst[e + 2]), u3 = __ldg(&lst[e + 3]);
        float4 v0 = *reinterpret_cast<const float4*>(hh + (size_t)u0 * 128 + lane * 4);
        float4 v1 = *reinterpret_cast<const float4*>(hh + (size_t)u1 * 128 + lane * 4);
        float4 v2 = *reinterpret_cast<const float4*>(hh + (size_t)u2 * 128 + lane * 4);
        float4 v3 = *reinterpret_cast<const float4*>(hh + (size_t)u3 * 128 + lane * 4);
        acc0.x += v0.x; acc0.y += v0.y; acc0.z += v0.z; acc0.w += v0.w;
        acc1.x += v1.x; acc1.y += v1.y; acc1.z += v1.z; acc1.w += v1.w;
        acc2.x += v2.x; acc2.y += v2.y; acc2.z += v2.z; acc2.w += v2.w;
        acc3.x += v3.x; acc3.y += v3.y; acc3.z += v3.z; acc3.w += v3.w;
    }
    for (; e < n; e++) {
        int u = __ldg(&lst[e]);
        float4 v = *reinterpret_cast<const float4*>(hh + (size_t)u * 128 + lane * 4);
        acc0.x += v.x; acc0.y += v.y; acc0.z += v.z; acc0.w += v.w;
    }
    acc0.x += acc1.x + acc2.x + acc3.x;
    acc0.y += acc1.y + acc2.y + acc3.y;
    acc0.z += acc1.z + acc2.z + acc3.z;
    acc0.w += acc1.w + acc2.w + acc3.w;
    float d = g_dis[w];
    float4 bb = *reinterpret_cast<const float4*>(bias + lane * 4);
    float4 r;
    r.x = acc0.x * d + bb.x; r.y = acc0.y * d + bb.y;
    r.z = acc0.z * d + bb.z; r.w = acc0.w * d + bb.w;
    if (relu) {
        r.x = fmaxf(r.x, 0.f); r.y = fmaxf(r.y, 0.f);
        r.z = fmaxf(r.z, 0.f); r.w = fmaxf(r.w, 0.f);
    }
    *reinterpret_cast<float4*>(g_bufB + (size_t)w * 128 + lane * 4) = r;
}

// ---------------- warp reductions ----------------
__device__ __forceinline__ float wredmax(float v) {
    #pragma unroll
    for (int o = 16; o; o >>= 1) v = fmaxf(v, __shfl_xor_sync(FULLM, v, o));
    return v;
}
__device__ __forceinline__ float wredsum(float v) {
    #pragma unroll
    for (int o = 16; o; o >>= 1) v += __shfl_xor_sync(FULLM, v, o);
    return v;
}

// ---------------- double softmax + mincut_den partial ----------------
__global__ void __launch_bounds__(256) k_softmax() {
    int n = (blockIdx.x * blockDim.x + threadIdx.x) >> 5;
    int lane = threadIdx.x & 31;
    if (n >= NN) return;
    float2 z = *reinterpret_cast<const float2*>(g_s_buf + (size_t)n * 64 + lane * 2);
    float m = wredmax(fmaxf(z.x, z.y));
    float ex = expf(z.x - m), ey = expf(z.y - m);
    float s = wredsum(ex + ey);
    float px = ex / s, py = ey / s;
    float m2 = wredmax(fmaxf(px, py));
    float ex2 = expf(px - m2), ey2 = expf(py - m2);
    float s2 = wredsum(ex2 + ey2);
    float qx = ex2 / s2, qy = ey2 / s2;
    *reinterpret_cast<float2*>(g_s_buf + (size_t)n * 64 + lane * 2) = make_float2(qx, qy);
    float t = wredsum(qx * qx + qy * qy);
    if (lane == 0) atomicAdd(&g_den[n >> 12], g_doutdeg[n] * t);
}

// ---------------- As[u] = sum_{u->v} s_d[v] ----------------
__global__ void __launch_bounds__(256) k_agg_as() {
    int w = (blockIdx.x * blockDim.x + threadIdx.x) >> 5;
    int lane = threadIdx.x & 31;
    if (w >= NN) return;
    float2 a0 = make_float2(0.f, 0.f), a1 = make_float2(0.f, 0.f);
    float2 a2 = make_float2(0.f, 0.f), a3 = make_float2(0.f, 0.f);
    int n = g_cnt_src[w];
    const int* lst = g_adj_src + (size_t)w * PAD;
    int e = 0;
    for (; e + 4 <= n; e += 4) {
        int v0 = __ldg(&lst[e]),     v1 = __ldg(&lst[e + 1]);
        int v2 = __ldg(&lst[e + 2]), v3 = __ldg(&lst[e + 3]);
        float2 t0 = *reinterpret_cast<const float2*>(g_s_buf + (size_t)v0 * 64 + lane * 2);
        float2 t1 = *reinterpret_cast<const float2*>(g_s_buf + (size_t)v1 * 64 + lane * 2);
        float2 t2 = *reinterpret_cast<const float2*>(g_s_buf + (size_t)v2 * 64 + lane * 2);
        float2 t3 = *reinterpret_cast<const float2*>(g_s_buf + (size_t)v3 * 64 + lane * 2);
        a0.x += t0.x; a0.y += t0.y;
        a1.x += t1.x; a1.y += t1.y;
        a2.x += t2.x; a2.y += t2.y;
        a3.x += t3.x; a3.y += t3.y;
    }
    for (; e < n; e++) {
        int v = __ldg(&lst[e]);
        float2 t = *reinterpret_cast<const float2*>(g_s_buf + (size_t)v * 64 + lane * 2);
        a0.x += t.x; a0.y += t.y;
    }
    a0.x += a1.x + a2.x + a3.x;
    a0.y += a1.y + a2.y + a3.y;
    *reinterpret_cast<float2*>(g_As + (size_t)w * 64 + lane * 2) = a0;
}

// ---------------- fused pooling reductions ----------------
__global__ void __launch_bounds__(256) k_pool() {
    int b = blockIdx.x >> 5;
    int chunk = blockIdx.x & 31;
    int tid = threadIdx.x;
    int ty = tid >> 4, tx = tid & 15;

    __shared__ float s_t[16][64];
    __shared__ float a_t[16][64];
    __shared__ float h_t[16][128];

    float racc[4][4] = {}, sacc[4][4] = {}, oacc[4][8] = {};

    for (int t = 0; t < 8; t++) {
        int nbase = b * NPG + chunk * 128 + t * 16;
        {
            int r = tid >> 4, c4 = (tid & 15) << 2;
            *reinterpret_cast<float4*>(&s_t[r][c4]) =
                *reinterpret_cast<const float4*>(g_s_buf + (size_t)(nbase + r) * 64 + c4);
            *reinterpret_cast<float4*>(&a_t[r][c4]) =
                *reinterpret_cast<const float4*>(g_As + (size_t)(nbase + r) * 64 + c4);
        }
        #pragma unroll
        for (int i = 0; i < 2; i++) {
            int idx = tid + i * 256;
            int r = idx >> 5, c4 = (idx & 31) << 2;
            *reinterpret_cast<float4*>(&h_t[r][c4]) =
                *reinterpret_cast<const float4*>(g_bufB + (size_t)(nbase + r) * 128 + c4);
        }
        __syncthreads();
        #pragma unroll
        for (int n = 0; n < 16; n++) {
            float4 skv = *reinterpret_cast<const float4*>(&s_t[n][ty * 4]);
            float4 ajv = *reinterpret_cast<const float4*>(&a_t[n][tx * 4]);
            float4 sjv = *reinterpret_cast<const float4*>(&s_t[n][tx * 4]);
            float4 h0v = *reinterpret_cast<const float4*>(&h_t[n][tx * 8]);
            float4 h1v = *reinterpret_cast<const float4*>(&h_t[n][tx * 8 + 4]);
            float sk[4] = {skv.x, skv.y, skv.z, skv.w};
            float aj[4] = {ajv.x, ajv.y, ajv.z, ajv.w};
            float sj[4] = {sjv.x, sjv.y, sjv.z, sjv.w};
            float hf[8] = {h0v.x, h0v.y, h0v.z, h0v.w, h1v.x, h1v.y, h1v.z, h1v.w};
            #pragma unroll
            for (int i = 0; i < 4; i++) {
                #pragma unroll
                for (int j = 0; j < 4; j++) {
                    racc[i][j] = fmaf(sk[i], aj[j], racc[i][j]);
                    sacc[i][j] = fmaf(sk[i], sj[j], sacc[i][j]);
                }
                #pragma unroll
                for (int j = 0; j < 8; j++)
                    oacc[i][j] = fmaf(sk[i], hf[j], oacc[i][j]);
            }
        }
        __syncthreads();
    }

    #pragma unroll
    for (int i = 0; i < 4; i++) {
        int k = ty * 4 + i;
        #pragma unroll
        for (int j = 0; j < 4; j++) {
            int c = tx * 4 + j;
            atomicAdd(&g_outadj[b * 4096 + k * 64 + c], racc[i][j]);
            atomicAdd(&g_ssm[b * 4096 + k * 64 + c], sacc[i][j]);
        }
        #pragma unroll
        for (int j = 0; j < 8; j++) {
            int f = tx * 8 + j;
            atomicAdd(&g_out_pool[(size_t)(b * 64 + k) * 128 + f], oacc[i][j]);
        }
    }
}

// ---------------- per-graph finalize ----------------
__device__ __forceinline__ float block_reduce256(float v, float* red) {
    int tid = threadIdx.x;
    red[tid] = v;
    __syncthreads();
    for (int s = 128; s > 0; s >>= 1) {
        if (tid < s) red[tid] += red[tid + s];
        __syncthreads();
    }
    float r = red[0];
    __syncthreads();
    return r;
}

__global__ void __launch_bounds__(256) k_finalize(float* __restrict__ out) {
    int b = blockIdx.x;
    int tid = threadIdx.x;
    __shared__ float oa[4096];
    __shared__ float red[256];
    __shared__ float dsh[64];

    for (int i = tid; i < 4096; i += 256) oa[i] = g_outadj[b * 4096 + i];
    __syncthreads();

    float tv = (tid < 64) ? oa[tid * 65] : 0.f;
    float trace = block_reduce256(tv, red);

    float s2 = 0.f;
    for (int i = tid; i < 4096; i += 256) {
        float v = g_ssm[b * 4096 + i];
        s2 += v * v;
    }
    float ssn = sqrtf(block_reduce256(s2, red));

    float o2 = 0.f;
    for (int i = tid; i < 4096; i += 256) {
        float v = g_ssm[b * 4096 + i] / ssn;
        if (i % 65 == 0) v -= 0.125f;
        o2 += v * v;
    }
    float ortho = sqrtf(block_reduce256(o2, red));

    if (tid < 64) {
        float rs = 0.f;
        for (int j = 0; j < 64; j++)
            if (j != tid) rs += oa[tid * 64 + j];
        dsh[tid] = sqrtf(rs) + 1e-15f;
    }
    __syncthreads();

    for (int i = tid; i < 4096; i += 256) {
        int k = i >> 6, j = i & 63;
        float v = (k == j) ? 0.f : oa[i] / (dsh[k] * dsh[j]);
        out[OA_OFF + b * 4096 + i] = v;
    }

    if (tid == 0) {
        g_mb[b] = -trace / g_den[b];
        g_ob[b] = ortho;
    }
}

__global__ void k_scalars(float* __restrict__ out) {
    int tid = threadIdx.x;
    out[PB_OFF + tid] = (float)(tid >> 6);
    if (tid == 0) {
        float m = 0.f, o = 0.f;
        for (int b = 0; b < NG; b++) { m += g_mb[b]; o += g_ob[b]; }
        out[ML_OFF] = m / (float)NG;
        out[OL_OFF] = o / (float)NG;
    }
}

// ---------------- launcher ----------------
extern "C" void kernel_launch(void* const* d_in, const int* in_sizes, int n_in,
                              void* d_out, int out_size) {
    (void)in_sizes; (void)n_in; (void)out_size;
    const float* x   = (const float*)d_in[0];
    const int*   ei  = (const int*)d_in[1];
    const float* W1  = (const float*)d_in[3];
    const float* b1  = (const float*)d_in[4];
    const float* W2  = (const float*)d_in[5];
    const float* b2  = (const float*)d_in[6];
    const float* Wa1 = (const float*)d_in[7];
    const float* ba1 = (const float*)d_in[8];
    const float* Wa2 = (const float*)d_in[9];
    const float* ba2 = (const float*)d_in[10];
    const float* Wo  = (const float*)d_in[11];
    const float* bo  = (const float*)d_in[12];
    float* out = (float*)d_out;
    const int* src = ei;
    const int* dst = ei + NE;

    const int SM128 = (128 * 2 + 128 * 2) * SROW * 2;   // 139264 B
    const int SM64  = (128 * 2 + 64 * 2) * SROW * 2;    // 104448 B
    cudaFuncSetAttribute(k_gemm_mma<128>, cudaFuncAttributeMaxDynamicSharedMemorySize, SM128);
    cudaFuncSetAttribute(k_gemm_mma<64>,  cudaFuncAttributeMaxDynamicSharedMemorySize, SM64);

    // 0: fused zero + all weight prep
    k_prep<<<256, 256>>>(W1, W2, Wa1, Wa2, Wo);
    // 1, 2: adjacency + norm
    k_scatter<<<512, 256>>>(src, dst);
    k_dis<<<128, 256>>>();

    // 3 (profiled): GCN layer 1 GEMM
    k_gemm_mma<128><<<NN / 128, 256, SM128>>>(x, -1, 0, nullptr, 1, nullptr, 0, 0);
    k_agg_f128<<<NN / 8, 256>>>(b1, 1);

    // GCN layer 2
    k_gemm_mma<128><<<NN / 128, 256, SM128>>>(nullptr, 1, 1, nullptr, 1, nullptr, 0, 0);
    k_agg_f128<<<NN / 8, 256>>>(b2, 0);

    // assignment MLP
    k_gemm_mma<128><<<NN / 128, 256, SM128>>>(nullptr, 1, 2, ba1, 0, nullptr, 0, 1);
    k_gemm_mma<64><<<NN / 128, 256, SM64>>>(nullptr, 0, 3, ba2, 0, nullptr, 2, 0);

    // double softmax (+ mincut_den), As = A @ s_d
    k_softmax<<<NN / 8, 256>>>();
    k_agg_as<<<NN / 8, 256>>>();

    // fused pooled reductions
    k_pool<<<NG * 32, 256>>>();

    // pooled_x = relu(out_pool @ Wo + bo) via MMA (512 rows -> 4 CTAs)
    k_gemm_mma<128><<<4, 256, SM128>>>(nullptr, 3, 4, bo, 0, out, -1, 2);

    k_finalize<<<NG, 256>>>(out);
    k_scalars<<<1, 512>>>(out);
}